// round 11
// baseline (speedup 1.0000x reference)
#include <cuda_runtime.h>
#include <cuda_fp16.h>
#include <cstdint>

#define Bb   64
#define Tt   320
#define Ee   1024
#define Hh   16
#define HS   64
#define NT   (Bb*Tt)
#define FF   (4*Ee)

__device__ __half g_h [NT*Ee];
__device__ __half g_q [NT*Ee];
__device__ __half g_k [NT*Ee];
__device__ __half g_v [NT*Ee];
__device__ float  g_x1[NT*Ee];
__device__ __half g_u [NT*FF];
__device__ __half g_w [12*1024*1024];

#define WOFF_Q  0
#define WOFF_O  (3*1024*1024)
#define WOFF_1  (4*1024*1024)
#define WOFF_2  (8*1024*1024)

__device__ __forceinline__ uint32_t h2u(float lo, float hi) {
    __half2 h = __floats2half2_rn(lo, hi);
    return *reinterpret_cast<uint32_t*>(&h);
}
__device__ __forceinline__ void cpa16(uint32_t dst, const void* src) {
    asm volatile("cp.async.cg.shared.global [%0], [%1], 16;" :: "r"(dst), "l"(src));
}
__device__ __forceinline__ void cpa_commit() { asm volatile("cp.async.commit_group;"); }

__device__ __forceinline__ void mma_f16(float* c, uint32_t a0, uint32_t a1,
                                        uint32_t a2, uint32_t a3,
                                        uint32_t b0, uint32_t b1) {
    asm volatile(
        "mma.sync.aligned.m16n8k16.row.col.f32.f16.f16.f32 "
        "{%0,%1,%2,%3}, {%4,%5,%6,%7}, {%8,%9}, {%0,%1,%2,%3};"
        : "+f"(c[0]), "+f"(c[1]), "+f"(c[2]), "+f"(c[3])
        : "r"(a0), "r"(a1), "r"(a2), "r"(a3), "r"(b0), "r"(b1));
}
__device__ __forceinline__ void ldsm4(uint32_t& r0, uint32_t& r1, uint32_t& r2,
                                      uint32_t& r3, uint32_t addr) {
    asm volatile("ldmatrix.sync.aligned.m8n8.x4.shared.b16 {%0,%1,%2,%3}, [%4];"
                 : "=r"(r0), "=r"(r1), "=r"(r2), "=r"(r3) : "r"(addr));
}
__device__ __forceinline__ void ldsm4t(uint32_t& r0, uint32_t& r1, uint32_t& r2,
                                       uint32_t& r3, uint32_t addr) {
    asm volatile("ldmatrix.sync.aligned.m8n8.x4.trans.shared.b16 {%0,%1,%2,%3}, [%4];"
                 : "=r"(r0), "=r"(r1), "=r"(r2), "=r"(r3) : "r"(addr));
}

// ---------------- prep: LN1 (blocks 0..NT-1) + weight fp32->fp16 convert ----------------
__global__ __launch_bounds__(256) void prep(
    const float* __restrict__ x, const float* __restrict__ ln1w,
    const float* __restrict__ ln1b, __half* __restrict__ hout,
    const float4* __restrict__ Wq, const float4* __restrict__ Wk,
    const float4* __restrict__ Wv, const float4* __restrict__ Wo,
    const float4* __restrict__ W1, const float4* __restrict__ W2,
    uint2* __restrict__ wdst)
{
    int blk = blockIdx.x;
    int tid = threadIdx.x;
    if (blk < NT) {
        __shared__ float red0[8], red1[8];
        size_t row = blk;
        const float4* xr = reinterpret_cast<const float4*>(x + row*Ee);
        float4 v4 = xr[tid];
        float s  = v4.x + v4.y + v4.z + v4.w;
        float s2 = v4.x*v4.x + v4.y*v4.y + v4.z*v4.z + v4.w*v4.w;
        #pragma unroll
        for (int off = 16; off; off >>= 1) {
            s  += __shfl_xor_sync(0xffffffffu, s,  off);
            s2 += __shfl_xor_sync(0xffffffffu, s2, off);
        }
        if ((tid & 31) == 0) { red0[tid>>5] = s; red1[tid>>5] = s2; }
        __syncthreads();
        if (tid == 0) {
            float a = 0.f, c = 0.f;
            #pragma unroll
            for (int i = 0; i < 8; i++) { a += red0[i]; c += red1[i]; }
            red0[0] = a; red1[0] = c;
        }
        __syncthreads();
        float mu  = red0[0] * (1.0f/Ee);
        float var = red1[0] * (1.0f/Ee) - mu*mu;
        float inv = rsqrtf(var + 1e-5f);
        float4 wv = reinterpret_cast<const float4*>(ln1w)[tid];
        float4 bv = reinterpret_cast<const float4*>(ln1b)[tid];
        uint2 pk;
        pk.x = h2u((v4.x - mu)*inv*wv.x + bv.x, (v4.y - mu)*inv*wv.y + bv.y);
        pk.y = h2u((v4.z - mu)*inv*wv.z + bv.z, (v4.w - mu)*inv*wv.w + bv.w);
        reinterpret_cast<uint2*>(hout + row*Ee)[tid] = pk;
    } else {
        int cb = blk - NT;
        #pragma unroll
        for (int it = 0; it < 4; it++) {
            int i = cb*1024 + it*256 + tid;
            const float4* src; int off;
            if      (i <  262144) { src = Wq; off = i; }
            else if (i <  524288) { src = Wk; off = i -  262144; }
            else if (i <  786432) { src = Wv; off = i -  524288; }
            else if (i < 1048576) { src = Wo; off = i -  786432; }
            else if (i < 2097152) { src = W1; off = i - 1048576; }
            else                  { src = W2; off = i - 2097152; }
            float4 v = src[off];
            uint2 p; p.x = h2u(v.x, v.y); p.y = h2u(v.z, v.w);
            wdst[i] = p;
        }
    }
}

// ---------------- LayerNorm fp32 -> half (LN2) ----------------
__global__ __launch_bounds__(256) void ln_h(
    const float* __restrict__ x, const float* __restrict__ w,
    const float* __restrict__ b, __half* __restrict__ out)
{
    __shared__ float red0[8], red1[8];
    int tid = threadIdx.x;
    size_t row = blockIdx.x;
    const float4* xr = reinterpret_cast<const float4*>(x + row*Ee);
    float4 v4 = xr[tid];
    float s  = v4.x + v4.y + v4.z + v4.w;
    float s2 = v4.x*v4.x + v4.y*v4.y + v4.z*v4.z + v4.w*v4.w;
    #pragma unroll
    for (int off = 16; off; off >>= 1) {
        s  += __shfl_xor_sync(0xffffffffu, s,  off);
        s2 += __shfl_xor_sync(0xffffffffu, s2, off);
    }
    if ((tid & 31) == 0) { red0[tid>>5] = s; red1[tid>>5] = s2; }
    __syncthreads();
    if (tid == 0) {
        float a = 0.f, c = 0.f;
        #pragma unroll
        for (int i = 0; i < 8; i++) { a += red0[i]; c += red1[i]; }
        red0[0] = a; red1[0] = c;
    }
    __syncthreads();
    float mu  = red0[0] * (1.0f/Ee);
    float var = red1[0] * (1.0f/Ee) - mu*mu;
    float inv = rsqrtf(var + 1e-5f);
    float4 wv = reinterpret_cast<const float4*>(w)[tid];
    float4 bv = reinterpret_cast<const float4*>(b)[tid];
    uint2 pk;
    pk.x = h2u((v4.x - mu)*inv*wv.x + bv.x, (v4.y - mu)*inv*wv.y + bv.y);
    pk.y = h2u((v4.z - mu)*inv*wv.z + bv.z, (v4.w - mu)*inv*wv.w + bv.w);
    reinterpret_cast<uint2*>(out + row*Ee)[tid] = pk;
}

// ===== fp16 GEMM: 128x128 CTA tile, BK=32, 4 stages, 4 warps of 64x64 =====
#define ASTRIDE  40                    // halfs per A smem row (80 B)
#define BSTRIDE  136                   // halfs per B smem row (272 B)
#define ABYTES   (128*ASTRIDE*2)       // 10240
#define STB      (ABYTES + 32*BSTRIDE*2)  // 18944
#define STAGES   4
#define GEMM_SMEM (STAGES*STB)         // 75776

template<bool RELU, bool RES, bool HALFOUT>
__global__ __launch_bounds__(128, 2) void gemm_f16(
    const __half* __restrict__ A, const __half* __restrict__ Bm,
    const float* __restrict__ bias, const float* __restrict__ res,
    void* __restrict__ Cout, int K, int N)
{
    extern __shared__ __half smh[];
    uint32_t smb = (uint32_t)__cvta_generic_to_shared(smh);
    int tid = threadIdx.x, lane = tid & 31, warp = tid >> 5;
    int wm = warp >> 1, wn = warp & 1;
    size_t row0 = (size_t)blockIdx.x * 128;
    int col0 = blockIdx.y * 128;

    // A: thread -> row tid, 4 chunks of 8 halfs; B: rows (tid>>4)+i*8, col (tid&15)*8
    const __half* aS = A + (row0 + tid) * (size_t)K;
    const __half* bS = Bm + (size_t)(tid >> 4) * N + col0 + (tid & 15) * 8;
    uint32_t dA = smb + tid * ASTRIDE * 2;
    uint32_t dB = smb + ABYTES + ((tid >> 4) * BSTRIDE + (tid & 15) * 8) * 2;

    float acc[4][8][4];
    #pragma unroll
    for (int i = 0; i < 4; i++)
        #pragma unroll
        for (int j = 0; j < 8; j++)
            #pragma unroll
            for (int r = 0; r < 4; r++) acc[i][j][r] = 0.f;

    const int KT = K >> 5;
    const size_t bRow8 = (size_t)8 * N;

    #pragma unroll
    for (int s = 0; s < STAGES - 1; s++) {
        uint32_t so = s * STB;
        const __half* ap = aS + s * 32;
        const __half* bp = bS + (size_t)s * 32 * N;
        #pragma unroll
        for (int i = 0; i < 4; i++) cpa16(dA + so + i * 16, ap + i * 8);
        #pragma unroll
        for (int i = 0; i < 4; i++) cpa16(dB + so + i * 8 * BSTRIDE * 2, bp + i * bRow8);
        cpa_commit();
    }

    uint32_t aLd = smb + (wm*64 + (lane & 15)) * ASTRIDE * 2 + (lane >> 4) * 16;
    uint32_t bLd = smb + ABYTES + (lane & 15) * BSTRIDE * 2
                       + (wn*64 + (lane >> 4) * 8) * 2;

    for (int kt = 0; kt < KT; ++kt) {
        asm volatile("cp.async.wait_group %0;" :: "n"(STAGES - 2));
        __syncthreads();
        int cur = kt % STAGES;
        int nk = kt + STAGES - 1;
        if (nk < KT) {
            uint32_t so = (nk % STAGES) * STB;
            const __half* ap = aS + nk * 32;
            const __half* bp = bS + (size_t)nk * 32 * N;
            #pragma unroll
            for (int i = 0; i < 4; i++) cpa16(dA + so + i * 16, ap + i * 8);
            #pragma unroll
            for (int i = 0; i < 4; i++) cpa16(dB + so + i * 8 * BSTRIDE * 2, bp + i * bRow8);
        }
        cpa_commit();

        uint32_t aB = aLd + cur * STB;
        uint32_t bB = bLd + cur * STB;
        #pragma unroll
        for (int ks = 0; ks < 2; ks++) {
            uint32_t b[4][4];
            #pragma unroll
            for (int njj = 0; njj < 4; njj++)
                ldsm4t(b[njj][0], b[njj][1], b[njj][2], b[njj][3],
                       bB + ks * 16 * BSTRIDE * 2 + njj * 32);
            #pragma unroll
            for (int mi = 0; mi < 4; mi++) {
                uint32_t a0, a1, a2, a3;
                ldsm4(a0, a1, a2, a3, aB + mi * 16 * ASTRIDE * 2 + ks * 32);
                #pragma unroll
                for (int njj = 0; njj < 4; njj++) {
                    mma_f16(acc[mi][njj*2],   a0, a1, a2, a3, b[njj][0], b[njj][1]);
                    mma_f16(acc[mi][njj*2+1], a0, a1, a2, a3, b[njj][2], b[njj][3]);
                }
            }
        }
    }

    #pragma unroll
    for (int mi = 0; mi < 4; mi++) {
        size_t r = row0 + wm*64 + mi*16 + (lane >> 2);
        #pragma unroll
        for (int nj = 0; nj < 8; nj++) {
            int c = col0 + wn*64 + nj*8 + 2*(lane & 3);
            float2 bb = *(const float2*)&bias[c];
            float v0 = acc[mi][nj][0] + bb.x, v1 = acc[mi][nj][1] + bb.y;
            float v2 = acc[mi][nj][2] + bb.x, v3 = acc[mi][nj][3] + bb.y;
            if (RELU) { v0=fmaxf(v0,0.f); v1=fmaxf(v1,0.f); v2=fmaxf(v2,0.f); v3=fmaxf(v3,0.f); }
            if (RES) {
                float2 r0 = *(const float2*)&res[r*(size_t)N + c];
                float2 r1 = *(const float2*)&res[(r+8)*(size_t)N + c];
                v0 += r0.x; v1 += r0.y; v2 += r1.x; v3 += r1.y;
            }
            if (HALFOUT) {
                __half* Ch = (__half*)Cout;
                *(uint32_t*)&Ch[r*(size_t)N + c]     = h2u(v0, v1);
                *(uint32_t*)&Ch[(r+8)*(size_t)N + c] = h2u(v2, v3);
            } else {
                float* Cf = (float*)Cout;
                float2 o0 = {v0, v1}, o1 = {v2, v3};
                *(float2*)&Cf[r*(size_t)N + c]     = o0;
                *(float2*)&Cf[(r+8)*(size_t)N + c] = o1;
            }
        }
    }
}

// ---------------- QKV projection (B per-head gather, scattered half output) ----------------
__global__ __launch_bounds__(128, 2) void qkv_f16(
    const __half* __restrict__ A, const __half* __restrict__ Wh,
    __half* __restrict__ qo, __half* __restrict__ ko, __half* __restrict__ vo)
{
    extern __shared__ __half smh[];
    uint32_t smb = (uint32_t)__cvta_generic_to_shared(smh);
    int tid = threadIdx.x, lane = tid & 31, warp = tid >> 5;
    int wm = warp >> 1, wn = warp & 1;
    size_t row0 = (size_t)blockIdx.x * 128;
    int col0 = blockIdx.y * 128;
    const int K = Ee;

    const __half* aS = A + (row0 + tid) * (size_t)K;
    int colT = col0 + (tid & 15) * 8;
    const __half* bS = Wh + ((size_t)(col0 >> 10) << 20)
                          + (size_t)((colT >> 6) & 15) * (Ee*HS)
                          + (size_t)(tid >> 4) * HS + (colT & 63);
    uint32_t dA = smb + tid * ASTRIDE * 2;
    uint32_t dB = smb + ABYTES + ((tid >> 4) * BSTRIDE + (tid & 15) * 8) * 2;

    float acc[4][8][4];
    #pragma unroll
    for (int i = 0; i < 4; i++)
        #pragma unroll
        for (int j = 0; j < 8; j++)
            #pragma unroll
            for (int r = 0; r < 4; r++) acc[i][j][r] = 0.f;

    const int KT = K >> 5;
    const size_t bRow8 = (size_t)8 * HS;

    #pragma unroll
    for (int s = 0; s < STAGES - 1; s++) {
        uint32_t so = s * STB;
        const __half* ap = aS + s * 32;
        const __half* bp = bS + (size_t)s * 32 * HS;
        #pragma unroll
        for (int i = 0; i < 4; i++) cpa16(dA + so + i * 16, ap + i * 8);
        #pragma unroll
        for (int i = 0; i < 4; i++) cpa16(dB + so + i * 8 * BSTRIDE * 2, bp + i * bRow8);
        cpa_commit();
    }

    uint32_t aLd = smb + (wm*64 + (lane & 15)) * ASTRIDE * 2 + (lane >> 4) * 16;
    uint32_t bLd = smb + ABYTES + (lane & 15) * BSTRIDE * 2
                       + (wn*64 + (lane >> 4) * 8) * 2;

    for (int kt = 0; kt < KT; ++kt) {
        asm volatile("cp.async.wait_group %0;" :: "n"(STAGES - 2));
        __syncthreads();
        int cur = kt % STAGES;
        int nk = kt + STAGES - 1;
        if (nk < KT) {
            uint32_t so = (nk % STAGES) * STB;
            const __half* ap = aS + nk * 32;
            const __half* bp = bS + (size_t)nk * 32 * HS;
            #pragma unroll
            for (int i = 0; i < 4; i++) cpa16(dA + so + i * 16, ap + i * 8);
            #pragma unroll
            for (int i = 0; i < 4; i++) cpa16(dB + so + i * 8 * BSTRIDE * 2, bp + i * bRow8);
        }
        cpa_commit();

        uint32_t aB = aLd + cur * STB;
        uint32_t bB = bLd + cur * STB;
        #pragma unroll
        for (int ks = 0; ks < 2; ks++) {
            uint32_t b[4][4];
            #pragma unroll
            for (int njj = 0; njj < 4; njj++)
                ldsm4t(b[njj][0], b[njj][1], b[njj][2], b[njj][3],
                       bB + ks * 16 * BSTRIDE * 2 + njj * 32);
            #pragma unroll
            for (int mi = 0; mi < 4; mi++) {
                uint32_t a0, a1, a2, a3;
                ldsm4(a0, a1, a2, a3, aB + mi * 16 * ASTRIDE * 2 + ks * 32);
                #pragma unroll
                for (int njj = 0; njj < 4; njj++) {
                    mma_f16(acc[mi][njj*2],   a0, a1, a2, a3, b[njj][0], b[njj][1]);
                    mma_f16(acc[mi][njj*2+1], a0, a1, a2, a3, b[njj][2], b[njj][3]);
                }
            }
        }
    }

    int which = col0 >> 10;
    __half* outp = (which == 0) ? qo : (which == 1) ? ko : vo;
    float scl = (which == 0) ? 0.04508422f : 1.0f;   // E^-0.5 * log2(e)
    #pragma unroll
    for (int mi = 0; mi < 4; mi++) {
        int r = (int)row0 + wm*64 + mi*16 + (lane >> 2);
        int b0r = r / Tt, t0 = r - b0r*Tt;
        int b1r = (r+8) / Tt, t1 = (r+8) - b1r*Tt;
        #pragma unroll
        for (int nj = 0; nj < 8; nj++) {
            int c = col0 + wn*64 + nj*8 + 2*(lane & 3);
            int hd = (c >> 6) & 15, d = c & 63;
            *(uint32_t*)&outp[((size_t)(b0r*Hh + hd)*Tt + t0)*HS + d] =
                h2u(acc[mi][nj][0]*scl, acc[mi][nj][1]*scl);
            *(uint32_t*)&outp[((size_t)(b1r*Hh + hd)*Tt + t1)*HS + d] =
                h2u(acc[mi][nj][2]*scl, acc[mi][nj][3]*scl);
        }
    }
}

// ---------------- fp16 mma.sync flash attention (exp2 domain) ----------------
__global__ __launch_bounds__(128) void attn_f16(
    const __half* __restrict__ q, const __half* __restrict__ k,
    const __half* __restrict__ v, __half* __restrict__ out)
{
    __shared__ __half Qs[64*72], Ks[64*72], Vs[64*72];
    int itile = blockIdx.x, bh = blockIdx.y;
    int tid = threadIdx.x, lane = tid & 31, w = tid >> 5;
    uint32_t qb = (uint32_t)__cvta_generic_to_shared(Qs);
    uint32_t kb = (uint32_t)__cvta_generic_to_shared(Ks);
    uint32_t vb = (uint32_t)__cvta_generic_to_shared(Vs);

    const __half* Qg = q + ((size_t)bh*Tt + itile*64)*HS;
    const __half* Kg = k + (size_t)bh*Tt*HS;
    const __half* Vg = v + (size_t)bh*Tt*HS;

    for (int i = tid; i < 512; i += 128) {
        int r = i >> 3, c = (i & 7) * 8;
        *(uint4*)&Qs[r*72 + c] = *(const uint4*)&Qg[r*HS + c];
    }

    float m0 = -1e30f, m1 = -1e30f, l0 = 0.f, l1 = 0.f;
    float o[8][4];
    #pragma unroll
    for (int i = 0; i < 8; i++)
        #pragma unroll
        for (int j = 0; j < 4; j++) o[i][j] = 0.f;

    uint32_t qaddr = qb + (w*16 + (lane & 15)) * 144 + (lane >> 4) * 16;

    for (int jt = 0; jt <= itile; jt++) {
        __syncthreads();
        const __half* Kt = Kg + jt*64*HS;
        const __half* Vt = Vg + jt*64*HS;
        for (int i = tid; i < 512; i += 128) {
            int r = i >> 3, c = (i & 7) * 8;
            *(uint4*)&Ks[r*72 + c] = *(const uint4*)&Kt[r*HS + c];
            *(uint4*)&Vs[r*72 + c] = *(const uint4*)&Vt[r*HS + c];
        }
        __syncthreads();

        float s[8][4];
        #pragma unroll
        for (int i = 0; i < 8; i++)
            #pragma unroll
            for (int j = 0; j < 4; j++) s[i][j] = 0.f;

        #pragma unroll
        for (int ks = 0; ks < 4; ks++) {
            uint32_t a0, a1, a2, a3;
            ldsm4(a0, a1, a2, a3, qaddr + ks*32);
            #pragma unroll
            for (int njj = 0; njj < 4; njj++) {
                uint32_t b0, b1, b2, b3;
                ldsm4(b0, b1, b2, b3, kb + (njj*16 + (lane & 15))*144 + (lane >> 4)*16 + ks*32);
                mma_f16(s[njj*2],   a0, a1, a2, a3, b0, b2);
                mma_f16(s[njj*2+1], a0, a1, a2, a3, b1, b3);
            }
        }

        if (jt == itile) {
            int r0 = w*16 + (lane >> 2), r1 = r0 + 8;
            #pragma unroll
            for (int nj = 0; nj < 8; nj++) {
                int cb = nj*8 + 2*(lane & 3);
                if (cb   > r0) s[nj][0] = -1e30f;
                if (cb+1 > r0) s[nj][1] = -1e30f;
                if (cb   > r1) s[nj][2] = -1e30f;
                if (cb+1 > r1) s[nj][3] = -1e30f;
            }
        }

        float mx0 = -1e30f, mx1 = -1e30f;
        #pragma unroll
        for (int nj = 0; nj < 8; nj++) {
            mx0 = fmaxf(mx0, fmaxf(s[nj][0], s[nj][1]));
            mx1 = fmaxf(mx1, fmaxf(s[nj][2], s[nj][3]));
        }
        mx0 = fmaxf(mx0, __shfl_xor_sync(0xffffffffu, mx0, 1));
        mx0 = fmaxf(mx0, __shfl_xor_sync(0xffffffffu, mx0, 2));
        mx1 = fmaxf(mx1, __shfl_xor_sync(0xffffffffu, mx1, 1));
        mx1 = fmaxf(mx1, __shfl_xor_sync(0xffffffffu, mx1, 2));
        float mn0 = fmaxf(m0, mx0), mn1 = fmaxf(m1, mx1);
        float c0 = exp2f(m0 - mn0), c1 = exp2f(m1 - mn1);
        float ps0 = 0.f, ps1 = 0.f;
        #pragma unroll
        for (int nj = 0; nj < 8; nj++) {
            s[nj][0] = exp2f(s[nj][0] - mn0); ps0 += s[nj][0];
            s[nj][1] = exp2f(s[nj][1] - mn0); ps0 += s[nj][1];
            s[nj][2] = exp2f(s[nj][2] - mn1); ps1 += s[nj][2];
            s[nj][3] = exp2f(s[nj][3] - mn1); ps1 += s[nj][3];
        }
        ps0 += __shfl_xor_sync(0xffffffffu, ps0, 1);
        ps0 += __shfl_xor_sync(0xffffffffu, ps0, 2);
        ps1 += __shfl_xor_sync(0xffffffffu, ps1, 1);
        ps1 += __shfl_xor_sync(0xffffffffu, ps1, 2);
        l0 = l0*c0 + ps0; l1 = l1*c1 + ps1;
        m0 = mn0; m1 = mn1;
        #pragma unroll
        for (int nj = 0; nj < 8; nj++) {
            o[nj][0] *= c0; o[nj][1] *= c0; o[nj][2] *= c1; o[nj][3] *= c1;
        }

        #pragma unroll
        for (int ks = 0; ks < 4; ks++) {
            uint32_t pa0 = h2u(s[2*ks][0],   s[2*ks][1]);
            uint32_t pa1 = h2u(s[2*ks][2],   s[2*ks][3]);
            uint32_t pa2 = h2u(s[2*ks+1][0], s[2*ks+1][1]);
            uint32_t pa3 = h2u(s[2*ks+1][2], s[2*ks+1][3]);
            #pragma unroll
            for (int njj = 0; njj < 4; njj++) {
                uint32_t b0, b1, b2, b3;
                ldsm4t(b0, b1, b2, b3, vb + (ks*16 + (lane & 15))*144
                                           + (njj*16 + (lane >> 4)*8)*2);
                mma_f16(o[njj*2],   pa0, pa1, pa2, pa3, b0, b1);
                mma_f16(o[njj*2+1], pa0, pa1, pa2, pa3, b2, b3);
            }
        }
    }

    int b = bh >> 4, head = bh & 15;
    float inv0 = 1.0f / l0, inv1 = 1.0f / l1;
    int trow = itile*64 + w*16 + (lane >> 2);
    __half* o0p = out + ((size_t)b*Tt + trow)*Ee + head*HS;
    __half* o1p = o0p + (size_t)8*Ee;
    #pragma unroll
    for (int nj = 0; nj < 8; nj++) {
        int c = nj*8 + 2*(lane & 3);
        *(uint32_t*)&o0p[c] = h2u(o[nj][0]*inv0, o[nj][1]*inv0);
        *(uint32_t*)&o1p[c] = h2u(o[nj][2]*inv1, o[nj][3]*inv1);
    }
}

extern "C" void kernel_launch(void* const* d_in, const int* in_sizes, int n_in,
                              void* d_out, int out_size)
{
    const float* x    = (const float*)d_in[0];
    const float* Wq   = (const float*)d_in[1];
    const float* Wk   = (const float*)d_in[2];
    const float* Wv   = (const float*)d_in[3];
    const float* Wo   = (const float*)d_in[4];
    const float* bo   = (const float*)d_in[5];
    const float* W1   = (const float*)d_in[6];
    const float* b1   = (const float*)d_in[7];
    const float* W2   = (const float*)d_in[8];
    const float* b2   = (const float*)d_in[9];
    const float* ln1w = (const float*)d_in[10];
    const float* ln1b = (const float*)d_in[11];
    const float* ln2w = (const float*)d_in[12];
    const float* ln2b = (const float*)d_in[13];
    float* out = (float*)d_out;

    __half *hP, *qP, *kP, *vP, *uP, *wP;
    float *x1P;
    cudaGetSymbolAddress((void**)&hP,  g_h);
    cudaGetSymbolAddress((void**)&qP,  g_q);
    cudaGetSymbolAddress((void**)&kP,  g_k);
    cudaGetSymbolAddress((void**)&vP,  g_v);
    cudaGetSymbolAddress((void**)&x1P, g_x1);
    cudaGetSymbolAddress((void**)&uP,  g_u);
    cudaGetSymbolAddress((void**)&wP,  g_w);

    cudaFuncSetAttribute(qkv_f16, cudaFuncAttributeMaxDynamicSharedMemorySize, GEMM_SMEM);
    cudaFuncSetAttribute(gemm_f16<false,true,false>, cudaFuncAttributeMaxDynamicSharedMemorySize, GEMM_SMEM);
    cudaFuncSetAttribute(gemm_f16<true,false,true>,  cudaFuncAttributeMaxDynamicSharedMemorySize, GEMM_SMEM);

    // 1) LN1 + all weight converts in ONE launch
    prep<<<NT + 3072, 256>>>(x, ln1w, ln1b, hP,
                             (const float4*)Wq, (const float4*)Wk, (const float4*)Wv,
                             (const float4*)Wo, (const float4*)W1, (const float4*)W2,
                             (uint2*)wP);
    // 2) q,k,v = h @ Wqkv
    qkv_f16<<<dim3(NT/128, 24), 128, GEMM_SMEM>>>(hP, wP, qP, kP, vP);
    // 3) attention -> g_h
    attn_f16<<<dim3(Tt/64, Bb*Hh), 128>>>(qP, kP, vP, hP);
    // 4) x1 = x + attn @ Wo + bo
    gemm_f16<false,true,false><<<dim3(NT/128, Ee/128), 128, GEMM_SMEM>>>(
        hP, wP+WOFF_O, bo, x, x1P, Ee, Ee);
    // 5) h2 = half(LN2(x1))
    ln_h<<<NT, 256>>>(x1P, ln2w, ln2b, qP);
    // 6) u = half(relu(h2 @ W1 + b1))
    gemm_f16<true,false,true><<<dim3(NT/128, FF/128), 128, GEMM_SMEM>>>(
        qP, wP+WOFF_1, b1, nullptr, uP, Ee, FF);
    // 7) out = x1 + u @ W2 + b2
    gemm_f16<false,true,false><<<dim3(NT/128, Ee/128), 128, GEMM_SMEM>>>(
        uP, wP+WOFF_2, b2, x1P, out, FF, Ee);
}

// round 12
// speedup vs baseline: 1.8696x; 1.8696x over previous
#include <cuda_runtime.h>
#include <cuda_fp16.h>
#include <cstdint>

#define Bb   64
#define Tt   320
#define Ee   1024
#define Hh   16
#define HS   64
#define NT   (Bb*Tt)
#define FF   (4*Ee)

__device__ __half g_h [NT*Ee];
__device__ __half g_q [NT*Ee];
__device__ __half g_k [NT*Ee];
__device__ __half g_v [NT*Ee];
__device__ float  g_x1[NT*Ee];
__device__ __half g_u [NT*FF];
__device__ __half g_w [12*1024*1024];

#define WOFF_Q  0
#define WOFF_O  (3*1024*1024)
#define WOFF_1  (4*1024*1024)
#define WOFF_2  (8*1024*1024)

__device__ __forceinline__ uint32_t h2u(float lo, float hi) {
    __half2 h = __floats2half2_rn(lo, hi);
    return *reinterpret_cast<uint32_t*>(&h);
}
__device__ __forceinline__ void cpa16(uint32_t dst, const void* src) {
    asm volatile("cp.async.cg.shared.global [%0], [%1], 16;" :: "r"(dst), "l"(src));
}
__device__ __forceinline__ void cpa_commit() { asm volatile("cp.async.commit_group;"); }

__device__ __forceinline__ void mma_f16(float* c, uint32_t a0, uint32_t a1,
                                        uint32_t a2, uint32_t a3,
                                        uint32_t b0, uint32_t b1) {
    asm volatile(
        "mma.sync.aligned.m16n8k16.row.col.f32.f16.f16.f32 "
        "{%0,%1,%2,%3}, {%4,%5,%6,%7}, {%8,%9}, {%0,%1,%2,%3};"
        : "+f"(c[0]), "+f"(c[1]), "+f"(c[2]), "+f"(c[3])
        : "r"(a0), "r"(a1), "r"(a2), "r"(a3), "r"(b0), "r"(b1));
}
__device__ __forceinline__ void ldsm4(uint32_t& r0, uint32_t& r1, uint32_t& r2,
                                      uint32_t& r3, uint32_t addr) {
    asm volatile("ldmatrix.sync.aligned.m8n8.x4.shared.b16 {%0,%1,%2,%3}, [%4];"
                 : "=r"(r0), "=r"(r1), "=r"(r2), "=r"(r3) : "r"(addr));
}
__device__ __forceinline__ void ldsm4t(uint32_t& r0, uint32_t& r1, uint32_t& r2,
                                       uint32_t& r3, uint32_t addr) {
    asm volatile("ldmatrix.sync.aligned.m8n8.x4.trans.shared.b16 {%0,%1,%2,%3}, [%4];"
                 : "=r"(r0), "=r"(r1), "=r"(r2), "=r"(r3) : "r"(addr));
}

// ---------------- prep: LN1 (blocks 0..NT-1) + weight fp32->fp16 convert ----------------
__global__ __launch_bounds__(256) void prep(
    const float* __restrict__ x, const float* __restrict__ ln1w,
    const float* __restrict__ ln1b, __half* __restrict__ hout,
    const float4* __restrict__ Wq, const float4* __restrict__ Wk,
    const float4* __restrict__ Wv, const float4* __restrict__ Wo,
    const float4* __restrict__ W1, const float4* __restrict__ W2,
    uint2* __restrict__ wdst)
{
    int blk = blockIdx.x;
    int tid = threadIdx.x;
    if (blk < NT) {
        __shared__ float red0[8], red1[8];
        size_t row = blk;
        const float4* xr = reinterpret_cast<const float4*>(x + row*Ee);
        float4 v4 = xr[tid];
        float s  = v4.x + v4.y + v4.z + v4.w;
        float s2 = v4.x*v4.x + v4.y*v4.y + v4.z*v4.z + v4.w*v4.w;
        #pragma unroll
        for (int off = 16; off; off >>= 1) {
            s  += __shfl_xor_sync(0xffffffffu, s,  off);
            s2 += __shfl_xor_sync(0xffffffffu, s2, off);
        }
        if ((tid & 31) == 0) { red0[tid>>5] = s; red1[tid>>5] = s2; }
        __syncthreads();
        if (tid == 0) {
            float a = 0.f, c = 0.f;
            #pragma unroll
            for (int i = 0; i < 8; i++) { a += red0[i]; c += red1[i]; }
            red0[0] = a; red1[0] = c;
        }
        __syncthreads();
        float mu  = red0[0] * (1.0f/Ee);
        float var = red1[0] * (1.0f/Ee) - mu*mu;
        float inv = rsqrtf(var + 1e-5f);
        float4 wv = reinterpret_cast<const float4*>(ln1w)[tid];
        float4 bv = reinterpret_cast<const float4*>(ln1b)[tid];
        uint2 pk;
        pk.x = h2u((v4.x - mu)*inv*wv.x + bv.x, (v4.y - mu)*inv*wv.y + bv.y);
        pk.y = h2u((v4.z - mu)*inv*wv.z + bv.z, (v4.w - mu)*inv*wv.w + bv.w);
        reinterpret_cast<uint2*>(hout + row*Ee)[tid] = pk;
    } else {
        int cb = blk - NT;
        #pragma unroll
        for (int it = 0; it < 4; it++) {
            int i = cb*1024 + it*256 + tid;
            const float4* src; int off;
            if      (i <  262144) { src = Wq; off = i; }
            else if (i <  524288) { src = Wk; off = i -  262144; }
            else if (i <  786432) { src = Wv; off = i -  524288; }
            else if (i < 1048576) { src = Wo; off = i -  786432; }
            else if (i < 2097152) { src = W1; off = i - 1048576; }
            else                  { src = W2; off = i - 2097152; }
            float4 v = src[off];
            uint2 p; p.x = h2u(v.x, v.y); p.y = h2u(v.z, v.w);
            wdst[i] = p;
        }
    }
}

// ---------------- LayerNorm fp32 -> half (LN2) ----------------
__global__ __launch_bounds__(256) void ln_h(
    const float* __restrict__ x, const float* __restrict__ w,
    const float* __restrict__ b, __half* __restrict__ out)
{
    __shared__ float red0[8], red1[8];
    int tid = threadIdx.x;
    size_t row = blockIdx.x;
    const float4* xr = reinterpret_cast<const float4*>(x + row*Ee);
    float4 v4 = xr[tid];
    float s  = v4.x + v4.y + v4.z + v4.w;
    float s2 = v4.x*v4.x + v4.y*v4.y + v4.z*v4.z + v4.w*v4.w;
    #pragma unroll
    for (int off = 16; off; off >>= 1) {
        s  += __shfl_xor_sync(0xffffffffu, s,  off);
        s2 += __shfl_xor_sync(0xffffffffu, s2, off);
    }
    if ((tid & 31) == 0) { red0[tid>>5] = s; red1[tid>>5] = s2; }
    __syncthreads();
    if (tid == 0) {
        float a = 0.f, c = 0.f;
        #pragma unroll
        for (int i = 0; i < 8; i++) { a += red0[i]; c += red1[i]; }
        red0[0] = a; red1[0] = c;
    }
    __syncthreads();
    float mu  = red0[0] * (1.0f/Ee);
    float var = red1[0] * (1.0f/Ee) - mu*mu;
    float inv = rsqrtf(var + 1e-5f);
    float4 wv = reinterpret_cast<const float4*>(w)[tid];
    float4 bv = reinterpret_cast<const float4*>(b)[tid];
    uint2 pk;
    pk.x = h2u((v4.x - mu)*inv*wv.x + bv.x, (v4.y - mu)*inv*wv.y + bv.y);
    pk.y = h2u((v4.z - mu)*inv*wv.z + bv.z, (v4.w - mu)*inv*wv.w + bv.w);
    reinterpret_cast<uint2*>(out + row*Ee)[tid] = pk;
}

// ===== fp16 GEMM: 64x128 CTA tile, BK=32, 4 stages, 4 warps of 64x32, 4 CTA/SM =====
#define ASTRIDE  40                    // halfs per A smem row (80 B)
#define BSTRIDE  136                   // halfs per B smem row (272 B)
#define ABYTES   (64*ASTRIDE*2)        // 5120
#define STB      (ABYTES + 32*BSTRIDE*2)  // 13824
#define STAGES   4
#define GEMM_SMEM (STAGES*STB)         // 55296

template<bool RELU, bool RES, bool HALFOUT>
__global__ __launch_bounds__(128, 4) void gemm_f16(
    const __half* __restrict__ A, const __half* __restrict__ Bm,
    const float* __restrict__ bias, const float* __restrict__ res,
    void* __restrict__ Cout, int K, int N)
{
    extern __shared__ __half smh[];
    uint32_t smb = (uint32_t)__cvta_generic_to_shared(smh);
    int tid = threadIdx.x, lane = tid & 31, wn = tid >> 5;
    size_t row0 = (size_t)blockIdx.x * 64;
    int col0 = blockIdx.y * 128;

    // A: thread pair covers one row (32 halfs); B: rows (tid>>4)+i*8, col (tid&15)*8
    const __half* aS = A + (row0 + (tid >> 1)) * (size_t)K + (tid & 1) * 16;
    const __half* bS = Bm + (size_t)(tid >> 4) * N + col0 + (tid & 15) * 8;
    uint32_t dA = smb + ((tid >> 1) * ASTRIDE + (tid & 1) * 16) * 2;
    uint32_t dB = smb + ABYTES + ((tid >> 4) * BSTRIDE + (tid & 15) * 8) * 2;

    float acc[4][4][4];
    #pragma unroll
    for (int i = 0; i < 4; i++)
        #pragma unroll
        for (int j = 0; j < 4; j++)
            #pragma unroll
            for (int r = 0; r < 4; r++) acc[i][j][r] = 0.f;

    const int KT = K >> 5;
    const size_t bRow8 = (size_t)8 * N;

    #pragma unroll
    for (int s = 0; s < STAGES - 1; s++) {
        uint32_t so = s * STB;
        const __half* ap = aS + s * 32;
        const __half* bp = bS + (size_t)s * 32 * N;
        cpa16(dA + so,      ap);
        cpa16(dA + so + 16, ap + 8);
        #pragma unroll
        for (int i = 0; i < 4; i++) cpa16(dB + so + i * 8 * BSTRIDE * 2, bp + i * bRow8);
        cpa_commit();
    }

    uint32_t aLd = smb + (lane & 15) * ASTRIDE * 2 + (lane >> 4) * 16;
    uint32_t bLd = smb + ABYTES + (lane & 15) * BSTRIDE * 2
                       + (wn*32 + (lane >> 4) * 8) * 2;

    for (int kt = 0; kt < KT; ++kt) {
        asm volatile("cp.async.wait_group %0;" :: "n"(STAGES - 2));
        __syncthreads();
        int cur = kt % STAGES;
        int nk = kt + STAGES - 1;
        if (nk < KT) {
            uint32_t so = (nk % STAGES) * STB;
            const __half* ap = aS + nk * 32;
            const __half* bp = bS + (size_t)nk * 32 * N;
            cpa16(dA + so,      ap);
            cpa16(dA + so + 16, ap + 8);
            #pragma unroll
            for (int i = 0; i < 4; i++) cpa16(dB + so + i * 8 * BSTRIDE * 2, bp + i * bRow8);
        }
        cpa_commit();

        uint32_t aB = aLd + cur * STB;
        uint32_t bB = bLd + cur * STB;
        #pragma unroll
        for (int ks = 0; ks < 2; ks++) {
            uint32_t b[2][4];
            #pragma unroll
            for (int njj = 0; njj < 2; njj++)
                ldsm4t(b[njj][0], b[njj][1], b[njj][2], b[njj][3],
                       bB + ks * 16 * BSTRIDE * 2 + njj * 32);
            #pragma unroll
            for (int mi = 0; mi < 4; mi++) {
                uint32_t a0, a1, a2, a3;
                ldsm4(a0, a1, a2, a3, aB + mi * 16 * ASTRIDE * 2 + ks * 32);
                #pragma unroll
                for (int njj = 0; njj < 2; njj++) {
                    mma_f16(acc[mi][njj*2],   a0, a1, a2, a3, b[njj][0], b[njj][1]);
                    mma_f16(acc[mi][njj*2+1], a0, a1, a2, a3, b[njj][2], b[njj][3]);
                }
            }
        }
    }

    #pragma unroll
    for (int mi = 0; mi < 4; mi++) {
        size_t r = row0 + mi*16 + (lane >> 2);
        #pragma unroll
        for (int nj = 0; nj < 4; nj++) {
            int c = col0 + wn*32 + nj*8 + 2*(lane & 3);
            float2 bb = *(const float2*)&bias[c];
            float v0 = acc[mi][nj][0] + bb.x, v1 = acc[mi][nj][1] + bb.y;
            float v2 = acc[mi][nj][2] + bb.x, v3 = acc[mi][nj][3] + bb.y;
            if (RELU) { v0=fmaxf(v0,0.f); v1=fmaxf(v1,0.f); v2=fmaxf(v2,0.f); v3=fmaxf(v3,0.f); }
            if (RES) {
                float2 r0 = *(const float2*)&res[r*(size_t)N + c];
                float2 r1 = *(const float2*)&res[(r+8)*(size_t)N + c];
                v0 += r0.x; v1 += r0.y; v2 += r1.x; v3 += r1.y;
            }
            if (HALFOUT) {
                __half* Ch = (__half*)Cout;
                *(uint32_t*)&Ch[r*(size_t)N + c]     = h2u(v0, v1);
                *(uint32_t*)&Ch[(r+8)*(size_t)N + c] = h2u(v2, v3);
            } else {
                float* Cf = (float*)Cout;
                float2 o0 = {v0, v1}, o1 = {v2, v3};
                *(float2*)&Cf[r*(size_t)N + c]     = o0;
                *(float2*)&Cf[(r+8)*(size_t)N + c] = o1;
            }
        }
    }
}

// ---------------- QKV projection (B per-head gather, scattered half output) ----------------
__global__ __launch_bounds__(128, 4) void qkv_f16(
    const __half* __restrict__ A, const __half* __restrict__ Wh,
    __half* __restrict__ qo, __half* __restrict__ ko, __half* __restrict__ vo)
{
    extern __shared__ __half smh[];
    uint32_t smb = (uint32_t)__cvta_generic_to_shared(smh);
    int tid = threadIdx.x, lane = tid & 31, wn = tid >> 5;
    size_t row0 = (size_t)blockIdx.x * 64;
    int col0 = blockIdx.y * 128;
    const int K = Ee;

    const __half* aS = A + (row0 + (tid >> 1)) * (size_t)K + (tid & 1) * 16;
    int colT = col0 + (tid & 15) * 8;
    const __half* bS = Wh + ((size_t)(col0 >> 10) << 20)
                          + (size_t)((colT >> 6) & 15) * (Ee*HS)
                          + (size_t)(tid >> 4) * HS + (colT & 63);
    uint32_t dA = smb + ((tid >> 1) * ASTRIDE + (tid & 1) * 16) * 2;
    uint32_t dB = smb + ABYTES + ((tid >> 4) * BSTRIDE + (tid & 15) * 8) * 2;

    float acc[4][4][4];
    #pragma unroll
    for (int i = 0; i < 4; i++)
        #pragma unroll
        for (int j = 0; j < 4; j++)
            #pragma unroll
            for (int r = 0; r < 4; r++) acc[i][j][r] = 0.f;

    const int KT = K >> 5;
    const size_t bRow8 = (size_t)8 * HS;

    #pragma unroll
    for (int s = 0; s < STAGES - 1; s++) {
        uint32_t so = s * STB;
        const __half* ap = aS + s * 32;
        const __half* bp = bS + (size_t)s * 32 * HS;
        cpa16(dA + so,      ap);
        cpa16(dA + so + 16, ap + 8);
        #pragma unroll
        for (int i = 0; i < 4; i++) cpa16(dB + so + i * 8 * BSTRIDE * 2, bp + i * bRow8);
        cpa_commit();
    }

    uint32_t aLd = smb + (lane & 15) * ASTRIDE * 2 + (lane >> 4) * 16;
    uint32_t bLd = smb + ABYTES + (lane & 15) * BSTRIDE * 2
                       + (wn*32 + (lane >> 4) * 8) * 2;

    for (int kt = 0; kt < KT; ++kt) {
        asm volatile("cp.async.wait_group %0;" :: "n"(STAGES - 2));
        __syncthreads();
        int cur = kt % STAGES;
        int nk = kt + STAGES - 1;
        if (nk < KT) {
            uint32_t so = (nk % STAGES) * STB;
            const __half* ap = aS + nk * 32;
            const __half* bp = bS + (size_t)nk * 32 * HS;
            cpa16(dA + so,      ap);
            cpa16(dA + so + 16, ap + 8);
            #pragma unroll
            for (int i = 0; i < 4; i++) cpa16(dB + so + i * 8 * BSTRIDE * 2, bp + i * bRow8);
        }
        cpa_commit();

        uint32_t aB = aLd + cur * STB;
        uint32_t bB = bLd + cur * STB;
        #pragma unroll
        for (int ks = 0; ks < 2; ks++) {
            uint32_t b[2][4];
            #pragma unroll
            for (int njj = 0; njj < 2; njj++)
                ldsm4t(b[njj][0], b[njj][1], b[njj][2], b[njj][3],
                       bB + ks * 16 * BSTRIDE * 2 + njj * 32);
            #pragma unroll
            for (int mi = 0; mi < 4; mi++) {
                uint32_t a0, a1, a2, a3;
                ldsm4(a0, a1, a2, a3, aB + mi * 16 * ASTRIDE * 2 + ks * 32);
                #pragma unroll
                for (int njj = 0; njj < 2; njj++) {
                    mma_f16(acc[mi][njj*2],   a0, a1, a2, a3, b[njj][0], b[njj][1]);
                    mma_f16(acc[mi][njj*2+1], a0, a1, a2, a3, b[njj][2], b[njj][3]);
                }
            }
        }
    }

    int which = col0 >> 10;
    __half* outp = (which == 0) ? qo : (which == 1) ? ko : vo;
    float scl = (which == 0) ? 0.04508422f : 1.0f;   // E^-0.5 * log2(e)
    #pragma unroll
    for (int mi = 0; mi < 4; mi++) {
        int r = (int)row0 + mi*16 + (lane >> 2);
        int b0r = r / Tt, t0 = r - b0r*Tt;
        int b1r = (r+8) / Tt, t1 = (r+8) - b1r*Tt;
        #pragma unroll
        for (int nj = 0; nj < 4; nj++) {
            int c = col0 + wn*32 + nj*8 + 2*(lane & 3);
            int hd = (c >> 6) & 15, d = c & 63;
            *(uint32_t*)&outp[((size_t)(b0r*Hh + hd)*Tt + t0)*HS + d] =
                h2u(acc[mi][nj][0]*scl, acc[mi][nj][1]*scl);
            *(uint32_t*)&outp[((size_t)(b1r*Hh + hd)*Tt + t1)*HS + d] =
                h2u(acc[mi][nj][2]*scl, acc[mi][nj][3]*scl);
        }
    }
}

// ---------------- fp16 mma.sync flash attention (exp2 domain) ----------------
__global__ __launch_bounds__(128) void attn_f16(
    const __half* __restrict__ q, const __half* __restrict__ k,
    const __half* __restrict__ v, __half* __restrict__ out)
{
    __shared__ __half Qs[64*72], Ks[64*72], Vs[64*72];
    int itile = blockIdx.x, bh = blockIdx.y;
    int tid = threadIdx.x, lane = tid & 31, w = tid >> 5;
    uint32_t qb = (uint32_t)__cvta_generic_to_shared(Qs);
    uint32_t kb = (uint32_t)__cvta_generic_to_shared(Ks);
    uint32_t vb = (uint32_t)__cvta_generic_to_shared(Vs);

    const __half* Qg = q + ((size_t)bh*Tt + itile*64)*HS;
    const __half* Kg = k + (size_t)bh*Tt*HS;
    const __half* Vg = v + (size_t)bh*Tt*HS;

    for (int i = tid; i < 512; i += 128) {
        int r = i >> 3, c = (i & 7) * 8;
        *(uint4*)&Qs[r*72 + c] = *(const uint4*)&Qg[r*HS + c];
    }

    float m0 = -1e30f, m1 = -1e30f, l0 = 0.f, l1 = 0.f;
    float o[8][4];
    #pragma unroll
    for (int i = 0; i < 8; i++)
        #pragma unroll
        for (int j = 0; j < 4; j++) o[i][j] = 0.f;

    uint32_t qaddr = qb + (w*16 + (lane & 15)) * 144 + (lane >> 4) * 16;

    for (int jt = 0; jt <= itile; jt++) {
        __syncthreads();
        const __half* Kt = Kg + jt*64*HS;
        const __half* Vt = Vg + jt*64*HS;
        for (int i = tid; i < 512; i += 128) {
            int r = i >> 3, c = (i & 7) * 8;
            *(uint4*)&Ks[r*72 + c] = *(const uint4*)&Kt[r*HS + c];
            *(uint4*)&Vs[r*72 + c] = *(const uint4*)&Vt[r*HS + c];
        }
        __syncthreads();

        float s[8][4];
        #pragma unroll
        for (int i = 0; i < 8; i++)
            #pragma unroll
            for (int j = 0; j < 4; j++) s[i][j] = 0.f;

        #pragma unroll
        for (int ks = 0; ks < 4; ks++) {
            uint32_t a0, a1, a2, a3;
            ldsm4(a0, a1, a2, a3, qaddr + ks*32);
            #pragma unroll
            for (int njj = 0; njj < 4; njj++) {
                uint32_t b0, b1, b2, b3;
                ldsm4(b0, b1, b2, b3, kb + (njj*16 + (lane & 15))*144 + (lane >> 4)*16 + ks*32);
                mma_f16(s[njj*2],   a0, a1, a2, a3, b0, b2);
                mma_f16(s[njj*2+1], a0, a1, a2, a3, b1, b3);
            }
        }

        if (jt == itile) {
            int r0 = w*16 + (lane >> 2), r1 = r0 + 8;
            #pragma unroll
            for (int nj = 0; nj < 8; nj++) {
                int cb = nj*8 + 2*(lane & 3);
                if (cb   > r0) s[nj][0] = -1e30f;
                if (cb+1 > r0) s[nj][1] = -1e30f;
                if (cb   > r1) s[nj][2] = -1e30f;
                if (cb+1 > r1) s[nj][3] = -1e30f;
            }
        }

        float mx0 = -1e30f, mx1 = -1e30f;
        #pragma unroll
        for (int nj = 0; nj < 8; nj++) {
            mx0 = fmaxf(mx0, fmaxf(s[nj][0], s[nj][1]));
            mx1 = fmaxf(mx1, fmaxf(s[nj][2], s[nj][3]));
        }
        mx0 = fmaxf(mx0, __shfl_xor_sync(0xffffffffu, mx0, 1));
        mx0 = fmaxf(mx0, __shfl_xor_sync(0xffffffffu, mx0, 2));
        mx1 = fmaxf(mx1, __shfl_xor_sync(0xffffffffu, mx1, 1));
        mx1 = fmaxf(mx1, __shfl_xor_sync(0xffffffffu, mx1, 2));
        float mn0 = fmaxf(m0, mx0), mn1 = fmaxf(m1, mx1);
        float c0 = exp2f(m0 - mn0), c1 = exp2f(m1 - mn1);
        float ps0 = 0.f, ps1 = 0.f;
        #pragma unroll
        for (int nj = 0; nj < 8; nj++) {
            s[nj][0] = exp2f(s[nj][0] - mn0); ps0 += s[nj][0];
            s[nj][1] = exp2f(s[nj][1] - mn0); ps0 += s[nj][1];
            s[nj][2] = exp2f(s[nj][2] - mn1); ps1 += s[nj][2];
            s[nj][3] = exp2f(s[nj][3] - mn1); ps1 += s[nj][3];
        }
        ps0 += __shfl_xor_sync(0xffffffffu, ps0, 1);
        ps0 += __shfl_xor_sync(0xffffffffu, ps0, 2);
        ps1 += __shfl_xor_sync(0xffffffffu, ps1, 1);
        ps1 += __shfl_xor_sync(0xffffffffu, ps1, 2);
        l0 = l0*c0 + ps0; l1 = l1*c1 + ps1;
        m0 = mn0; m1 = mn1;
        #pragma unroll
        for (int nj = 0; nj < 8; nj++) {
            o[nj][0] *= c0; o[nj][1] *= c0; o[nj][2] *= c1; o[nj][3] *= c1;
        }

        #pragma unroll
        for (int ks = 0; ks < 4; ks++) {
            uint32_t pa0 = h2u(s[2*ks][0],   s[2*ks][1]);
            uint32_t pa1 = h2u(s[2*ks][2],   s[2*ks][3]);
            uint32_t pa2 = h2u(s[2*ks+1][0], s[2*ks+1][1]);
            uint32_t pa3 = h2u(s[2*ks+1][2], s[2*ks+1][3]);
            #pragma unroll
            for (int njj = 0; njj < 4; njj++) {
                uint32_t b0, b1, b2, b3;
                ldsm4t(b0, b1, b2, b3, vb + (ks*16 + (lane & 15))*144
                                           + (njj*16 + (lane >> 4)*8)*2);
                mma_f16(o[njj*2],   pa0, pa1, pa2, pa3, b0, b1);
                mma_f16(o[njj*2+1], pa0, pa1, pa2, pa3, b2, b3);
            }
        }
    }

    int b = bh >> 4, head = bh & 15;
    float inv0 = 1.0f / l0, inv1 = 1.0f / l1;
    int trow = itile*64 + w*16 + (lane >> 2);
    __half* o0p = out + ((size_t)b*Tt + trow)*Ee + head*HS;
    __half* o1p = o0p + (size_t)8*Ee;
    #pragma unroll
    for (int nj = 0; nj < 8; nj++) {
        int c = nj*8 + 2*(lane & 3);
        *(uint32_t*)&o0p[c] = h2u(o[nj][0]*inv0, o[nj][1]*inv0);
        *(uint32_t*)&o1p[c] = h2u(o[nj][2]*inv1, o[nj][3]*inv1);
    }
}

extern "C" void kernel_launch(void* const* d_in, const int* in_sizes, int n_in,
                              void* d_out, int out_size)
{
    const float* x    = (const float*)d_in[0];
    const float* Wq   = (const float*)d_in[1];
    const float* Wk   = (const float*)d_in[2];
    const float* Wv   = (const float*)d_in[3];
    const float* Wo   = (const float*)d_in[4];
    const float* bo   = (const float*)d_in[5];
    const float* W1   = (const float*)d_in[6];
    const float* b1   = (const float*)d_in[7];
    const float* W2   = (const float*)d_in[8];
    const float* b2   = (const float*)d_in[9];
    const float* ln1w = (const float*)d_in[10];
    const float* ln1b = (const float*)d_in[11];
    const float* ln2w = (const float*)d_in[12];
    const float* ln2b = (const float*)d_in[13];
    float* out = (float*)d_out;

    __half *hP, *qP, *kP, *vP, *uP, *wP;
    float *x1P;
    cudaGetSymbolAddress((void**)&hP,  g_h);
    cudaGetSymbolAddress((void**)&qP,  g_q);
    cudaGetSymbolAddress((void**)&kP,  g_k);
    cudaGetSymbolAddress((void**)&vP,  g_v);
    cudaGetSymbolAddress((void**)&x1P, g_x1);
    cudaGetSymbolAddress((void**)&uP,  g_u);
    cudaGetSymbolAddress((void**)&wP,  g_w);

    cudaFuncSetAttribute(qkv_f16, cudaFuncAttributeMaxDynamicSharedMemorySize, GEMM_SMEM);
    cudaFuncSetAttribute(gemm_f16<false,true,false>, cudaFuncAttributeMaxDynamicSharedMemorySize, GEMM_SMEM);
    cudaFuncSetAttribute(gemm_f16<true,false,true>,  cudaFuncAttributeMaxDynamicSharedMemorySize, GEMM_SMEM);

    // 1) LN1 + all weight converts in ONE launch
    prep<<<NT + 3072, 256>>>(x, ln1w, ln1b, hP,
                             (const float4*)Wq, (const float4*)Wk, (const float4*)Wv,
                             (const float4*)Wo, (const float4*)W1, (const float4*)W2,
                             (uint2*)wP);
    // 2) q,k,v = h @ Wqkv
    qkv_f16<<<dim3(NT/64, 24), 128, GEMM_SMEM>>>(hP, wP, qP, kP, vP);
    // 3) attention -> g_h
    attn_f16<<<dim3(Tt/64, Bb*Hh), 128>>>(qP, kP, vP, hP);
    // 4) x1 = x + attn @ Wo + bo
    gemm_f16<false,true,false><<<dim3(NT/64, Ee/128), 128, GEMM_SMEM>>>(
        hP, wP+WOFF_O, bo, x, x1P, Ee, Ee);
    // 5) h2 = half(LN2(x1))
    ln_h<<<NT, 256>>>(x1P, ln2w, ln2b, qP);
    // 6) u = half(relu(h2 @ W1 + b1))
    gemm_f16<true,false,true><<<dim3(NT/64, FF/128), 128, GEMM_SMEM>>>(
        qP, wP+WOFF_1, b1, nullptr, uP, Ee, FF);
    // 7) out = x1 + u @ W2 + b2
    gemm_f16<false,true,false><<<dim3(NT/64, Ee/128), 128, GEMM_SMEM>>>(
        uP, wP+WOFF_2, b2, x1P, out, FF, Ee);
}

// round 13
// speedup vs baseline: 1.9238x; 1.0290x over previous
#include <cuda_runtime.h>
#include <cuda_fp16.h>
#include <cstdint>

#define Bb   64
#define Tt   320
#define Ee   1024
#define Hh   16
#define HS   64
#define NT   (Bb*Tt)
#define FF   (4*Ee)

__device__ __half g_h [NT*Ee];
__device__ __half g_q [NT*Ee];
__device__ __half g_k [NT*Ee];
__device__ __half g_v [NT*Ee];
__device__ float  g_x1[NT*Ee];
__device__ __half g_u [NT*FF];
__device__ __half g_w [12*1024*1024];

#define WOFF_Q  0
#define WOFF_O  (3*1024*1024)
#define WOFF_1  (4*1024*1024)
#define WOFF_2  (8*1024*1024)

__device__ __forceinline__ uint32_t h2u(float lo, float hi) {
    __half2 h = __floats2half2_rn(lo, hi);
    return *reinterpret_cast<uint32_t*>(&h);
}
__device__ __forceinline__ void cpa16(uint32_t dst, const void* src) {
    asm volatile("cp.async.cg.shared.global [%0], [%1], 16;" :: "r"(dst), "l"(src));
}
__device__ __forceinline__ void cpa_commit() { asm volatile("cp.async.commit_group;"); }

__device__ __forceinline__ void mma_f16(float* c, uint32_t a0, uint32_t a1,
                                        uint32_t a2, uint32_t a3,
                                        uint32_t b0, uint32_t b1) {
    asm volatile(
        "mma.sync.aligned.m16n8k16.row.col.f32.f16.f16.f32 "
        "{%0,%1,%2,%3}, {%4,%5,%6,%7}, {%8,%9}, {%0,%1,%2,%3};"
        : "+f"(c[0]), "+f"(c[1]), "+f"(c[2]), "+f"(c[3])
        : "r"(a0), "r"(a1), "r"(a2), "r"(a3), "r"(b0), "r"(b1));
}
__device__ __forceinline__ void ldsm4(uint32_t& r0, uint32_t& r1, uint32_t& r2,
                                      uint32_t& r3, uint32_t addr) {
    asm volatile("ldmatrix.sync.aligned.m8n8.x4.shared.b16 {%0,%1,%2,%3}, [%4];"
                 : "=r"(r0), "=r"(r1), "=r"(r2), "=r"(r3) : "r"(addr));
}
__device__ __forceinline__ void ldsm4t(uint32_t& r0, uint32_t& r1, uint32_t& r2,
                                       uint32_t& r3, uint32_t addr) {
    asm volatile("ldmatrix.sync.aligned.m8n8.x4.trans.shared.b16 {%0,%1,%2,%3}, [%4];"
                 : "=r"(r0), "=r"(r1), "=r"(r2), "=r"(r3) : "r"(addr));
}

// ---------------- prep: LN1 (blocks 0..NT-1) + weight fp32->fp16 convert ----------------
__global__ __launch_bounds__(256) void prep(
    const float* __restrict__ x, const float* __restrict__ ln1w,
    const float* __restrict__ ln1b, __half* __restrict__ hout,
    const float4* __restrict__ Wq, const float4* __restrict__ Wk,
    const float4* __restrict__ Wv, const float4* __restrict__ Wo,
    const float4* __restrict__ W1, const float4* __restrict__ W2,
    uint2* __restrict__ wdst)
{
    int blk = blockIdx.x;
    int tid = threadIdx.x;
    if (blk < NT) {
        __shared__ float red0[8], red1[8];
        size_t row = blk;
        const float4* xr = reinterpret_cast<const float4*>(x + row*Ee);
        float4 v4 = xr[tid];
        float s  = v4.x + v4.y + v4.z + v4.w;
        float s2 = v4.x*v4.x + v4.y*v4.y + v4.z*v4.z + v4.w*v4.w;
        #pragma unroll
        for (int off = 16; off; off >>= 1) {
            s  += __shfl_xor_sync(0xffffffffu, s,  off);
            s2 += __shfl_xor_sync(0xffffffffu, s2, off);
        }
        if ((tid & 31) == 0) { red0[tid>>5] = s; red1[tid>>5] = s2; }
        __syncthreads();
        if (tid == 0) {
            float a = 0.f, c = 0.f;
            #pragma unroll
            for (int i = 0; i < 8; i++) { a += red0[i]; c += red1[i]; }
            red0[0] = a; red1[0] = c;
        }
        __syncthreads();
        float mu  = red0[0] * (1.0f/Ee);
        float var = red1[0] * (1.0f/Ee) - mu*mu;
        float inv = rsqrtf(var + 1e-5f);
        float4 wv = reinterpret_cast<const float4*>(ln1w)[tid];
        float4 bv = reinterpret_cast<const float4*>(ln1b)[tid];
        uint2 pk;
        pk.x = h2u((v4.x - mu)*inv*wv.x + bv.x, (v4.y - mu)*inv*wv.y + bv.y);
        pk.y = h2u((v4.z - mu)*inv*wv.z + bv.z, (v4.w - mu)*inv*wv.w + bv.w);
        reinterpret_cast<uint2*>(hout + row*Ee)[tid] = pk;
    } else {
        int cb = blk - NT;
        #pragma unroll
        for (int it = 0; it < 4; it++) {
            int i = cb*1024 + it*256 + tid;
            const float4* src; int off;
            if      (i <  262144) { src = Wq; off = i; }
            else if (i <  524288) { src = Wk; off = i -  262144; }
            else if (i <  786432) { src = Wv; off = i -  524288; }
            else if (i < 1048576) { src = Wo; off = i -  786432; }
            else if (i < 2097152) { src = W1; off = i - 1048576; }
            else                  { src = W2; off = i - 2097152; }
            float4 v = src[off];
            uint2 p; p.x = h2u(v.x, v.y); p.y = h2u(v.z, v.w);
            wdst[i] = p;
        }
    }
}

// ---------------- LayerNorm fp32 -> half (LN2) ----------------
__global__ __launch_bounds__(256) void ln_h(
    const float* __restrict__ x, const float* __restrict__ w,
    const float* __restrict__ b, __half* __restrict__ out)
{
    __shared__ float red0[8], red1[8];
    int tid = threadIdx.x;
    size_t row = blockIdx.x;
    const float4* xr = reinterpret_cast<const float4*>(x + row*Ee);
    float4 v4 = xr[tid];
    float s  = v4.x + v4.y + v4.z + v4.w;
    float s2 = v4.x*v4.x + v4.y*v4.y + v4.z*v4.z + v4.w*v4.w;
    #pragma unroll
    for (int off = 16; off; off >>= 1) {
        s  += __shfl_xor_sync(0xffffffffu, s,  off);
        s2 += __shfl_xor_sync(0xffffffffu, s2, off);
    }
    if ((tid & 31) == 0) { red0[tid>>5] = s; red1[tid>>5] = s2; }
    __syncthreads();
    if (tid == 0) {
        float a = 0.f, c = 0.f;
        #pragma unroll
        for (int i = 0; i < 8; i++) { a += red0[i]; c += red1[i]; }
        red0[0] = a; red1[0] = c;
    }
    __syncthreads();
    float mu  = red0[0] * (1.0f/Ee);
    float var = red1[0] * (1.0f/Ee) - mu*mu;
    float inv = rsqrtf(var + 1e-5f);
    float4 wv = reinterpret_cast<const float4*>(w)[tid];
    float4 bv = reinterpret_cast<const float4*>(b)[tid];
    uint2 pk;
    pk.x = h2u((v4.x - mu)*inv*wv.x + bv.x, (v4.y - mu)*inv*wv.y + bv.y);
    pk.y = h2u((v4.z - mu)*inv*wv.z + bv.z, (v4.w - mu)*inv*wv.w + bv.w);
    reinterpret_cast<uint2*>(out + row*Ee)[tid] = pk;
}

// ===== fp16 GEMM: 128x128 CTA tile, BK=32, 5 stages, 8 warps of 64x32, 2 CTA/SM =====
#define ASTRIDE  40                    // halfs per A smem row (80 B)
#define BSTRIDE  136                   // halfs per B smem row (272 B)
#define ABYTES   (128*ASTRIDE*2)       // 10240
#define STB      (ABYTES + 32*BSTRIDE*2)  // 18944
#define STAGES   5
#define GEMM_SMEM (STAGES*STB)         // 94720

template<bool RELU, bool RES, bool HALFOUT>
__global__ __launch_bounds__(256, 2) void gemm_f16(
    const __half* __restrict__ A, const __half* __restrict__ Bm,
    const float* __restrict__ bias, const float* __restrict__ res,
    void* __restrict__ Cout, int K, int N)
{
    extern __shared__ __half smh[];
    uint32_t smb = (uint32_t)__cvta_generic_to_shared(smh);
    int tid = threadIdx.x, lane = tid & 31, warp = tid >> 5;
    int wm = warp >> 2, wn = warp & 3;
    size_t row0 = (size_t)blockIdx.x * 128;
    int col0 = blockIdx.y * 128;

    const __half* aS0 = A + (row0 + (tid >> 2)) * (size_t)K + (tid & 3) * 8;
    const __half* aS1 = aS0 + (size_t)64 * K;
    const __half* bS0 = Bm + (size_t)(tid >> 4) * N + col0 + (tid & 15) * 8;
    const __half* bS1 = bS0 + (size_t)16 * N;
    uint32_t dA0 = smb + ((tid >> 2) * ASTRIDE + (tid & 3) * 8) * 2;
    uint32_t dA1 = dA0 + 64 * ASTRIDE * 2;
    uint32_t dB0 = smb + ABYTES + ((tid >> 4) * BSTRIDE + (tid & 15) * 8) * 2;
    uint32_t dB1 = dB0 + 16 * BSTRIDE * 2;

    float acc[4][4][4];
    #pragma unroll
    for (int i = 0; i < 4; i++)
        #pragma unroll
        for (int j = 0; j < 4; j++)
            #pragma unroll
            for (int r = 0; r < 4; r++) acc[i][j][r] = 0.f;

    const int KT = K >> 5;
    #pragma unroll
    for (int s = 0; s < STAGES - 1; s++) {
        uint32_t so = s * STB;
        cpa16(dA0 + so, aS0 + s * 32);
        cpa16(dA1 + so, aS1 + s * 32);
        cpa16(dB0 + so, bS0 + (size_t)s * 32 * N);
        cpa16(dB1 + so, bS1 + (size_t)s * 32 * N);
        cpa_commit();
    }

    uint32_t aLd = smb + (wm*64 + (lane & 15)) * ASTRIDE * 2 + (lane >> 4) * 16;
    uint32_t bLd = smb + ABYTES + (lane & 15) * BSTRIDE * 2
                       + (wn*32 + (lane >> 4) * 8) * 2;

    for (int kt = 0; kt < KT; ++kt) {
        asm volatile("cp.async.wait_group %0;" :: "n"(STAGES - 2));
        __syncthreads();
        int cur = kt % STAGES;
        int nk = kt + STAGES - 1;
        if (nk < KT) {
            uint32_t so = (nk % STAGES) * STB;
            cpa16(dA0 + so, aS0 + nk * 32);
            cpa16(dA1 + so, aS1 + nk * 32);
            cpa16(dB0 + so, bS0 + (size_t)nk * 32 * N);
            cpa16(dB1 + so, bS1 + (size_t)nk * 32 * N);
        }
        cpa_commit();

        uint32_t aB = aLd + cur * STB;
        uint32_t bB = bLd + cur * STB;
        #pragma unroll
        for (int ks = 0; ks < 2; ks++) {
            uint32_t b[2][4];
            #pragma unroll
            for (int njj = 0; njj < 2; njj++)
                ldsm4t(b[njj][0], b[njj][1], b[njj][2], b[njj][3],
                       bB + ks * 16 * BSTRIDE * 2 + njj * 32);
            #pragma unroll
            for (int mi = 0; mi < 4; mi++) {
                uint32_t a0, a1, a2, a3;
                ldsm4(a0, a1, a2, a3, aB + mi * 16 * ASTRIDE * 2 + ks * 32);
                #pragma unroll
                for (int njj = 0; njj < 2; njj++) {
                    mma_f16(acc[mi][njj*2],   a0, a1, a2, a3, b[njj][0], b[njj][1]);
                    mma_f16(acc[mi][njj*2+1], a0, a1, a2, a3, b[njj][2], b[njj][3]);
                }
            }
        }
    }

    #pragma unroll
    for (int mi = 0; mi < 4; mi++) {
        size_t r = row0 + wm*64 + mi*16 + (lane >> 2);
        #pragma unroll
        for (int nj = 0; nj < 4; nj++) {
            int c = col0 + wn*32 + nj*8 + 2*(lane & 3);
            float2 bb = *(const float2*)&bias[c];
            float v0 = acc[mi][nj][0] + bb.x, v1 = acc[mi][nj][1] + bb.y;
            float v2 = acc[mi][nj][2] + bb.x, v3 = acc[mi][nj][3] + bb.y;
            if (RELU) { v0=fmaxf(v0,0.f); v1=fmaxf(v1,0.f); v2=fmaxf(v2,0.f); v3=fmaxf(v3,0.f); }
            if (RES) {
                float2 r0 = *(const float2*)&res[r*(size_t)N + c];
                float2 r1 = *(const float2*)&res[(r+8)*(size_t)N + c];
                v0 += r0.x; v1 += r0.y; v2 += r1.x; v3 += r1.y;
            }
            if (HALFOUT) {
                __half* Ch = (__half*)Cout;
                *(uint32_t*)&Ch[r*(size_t)N + c]     = h2u(v0, v1);
                *(uint32_t*)&Ch[(r+8)*(size_t)N + c] = h2u(v2, v3);
            } else {
                float* Cf = (float*)Cout;
                float2 o0 = {v0, v1}, o1 = {v2, v3};
                *(float2*)&Cf[r*(size_t)N + c]     = o0;
                *(float2*)&Cf[(r+8)*(size_t)N + c] = o1;
            }
        }
    }
}

// ---------------- QKV projection (B per-head gather, scattered half output) ----------------
__global__ __launch_bounds__(256, 2) void qkv_f16(
    const __half* __restrict__ A, const __half* __restrict__ Wh,
    __half* __restrict__ qo, __half* __restrict__ ko, __half* __restrict__ vo)
{
    extern __shared__ __half smh[];
    uint32_t smb = (uint32_t)__cvta_generic_to_shared(smh);
    int tid = threadIdx.x, lane = tid & 31, warp = tid >> 5;
    int wm = warp >> 2, wn = warp & 3;
    size_t row0 = (size_t)blockIdx.x * 128;
    int col0 = blockIdx.y * 128;
    const int K = Ee;

    const __half* aS0 = A + (row0 + (tid >> 2)) * (size_t)K + (tid & 3) * 8;
    const __half* aS1 = aS0 + (size_t)64 * K;
    int colT = col0 + (tid & 15) * 8;
    const __half* bS0 = Wh + ((size_t)(col0 >> 10) << 20)
                           + (size_t)((colT >> 6) & 15) * (Ee*HS)
                           + (size_t)(tid >> 4) * HS + (colT & 63);
    const __half* bS1 = bS0 + 16 * HS;

    uint32_t dA0 = smb + ((tid >> 2) * ASTRIDE + (tid & 3) * 8) * 2;
    uint32_t dA1 = dA0 + 64 * ASTRIDE * 2;
    uint32_t dB0 = smb + ABYTES + ((tid >> 4) * BSTRIDE + (tid & 15) * 8) * 2;
    uint32_t dB1 = dB0 + 16 * BSTRIDE * 2;

    float acc[4][4][4];
    #pragma unroll
    for (int i = 0; i < 4; i++)
        #pragma unroll
        for (int j = 0; j < 4; j++)
            #pragma unroll
            for (int r = 0; r < 4; r++) acc[i][j][r] = 0.f;

    const int KT = K >> 5;
    #pragma unroll
    for (int s = 0; s < STAGES - 1; s++) {
        uint32_t so = s * STB;
        cpa16(dA0 + so, aS0 + s * 32);
        cpa16(dA1 + so, aS1 + s * 32);
        cpa16(dB0 + so, bS0 + s * 32 * HS);
        cpa16(dB1 + so, bS1 + s * 32 * HS);
        cpa_commit();
    }

    uint32_t aLd = smb + (wm*64 + (lane & 15)) * ASTRIDE * 2 + (lane >> 4) * 16;
    uint32_t bLd = smb + ABYTES + (lane & 15) * BSTRIDE * 2
                       + (wn*32 + (lane >> 4) * 8) * 2;

    for (int kt = 0; kt < KT; ++kt) {
        asm volatile("cp.async.wait_group %0;" :: "n"(STAGES - 2));
        __syncthreads();
        int cur = kt % STAGES;
        int nk = kt + STAGES - 1;
        if (nk < KT) {
            uint32_t so = (nk % STAGES) * STB;
            cpa16(dA0 + so, aS0 + nk * 32);
            cpa16(dA1 + so, aS1 + nk * 32);
            cpa16(dB0 + so, bS0 + nk * 32 * HS);
            cpa16(dB1 + so, bS1 + nk * 32 * HS);
        }
        cpa_commit();

        uint32_t aB = aLd + cur * STB;
        uint32_t bB = bLd + cur * STB;
        #pragma unroll
        for (int ks = 0; ks < 2; ks++) {
            uint32_t b[2][4];
            #pragma unroll
            for (int njj = 0; njj < 2; njj++)
                ldsm4t(b[njj][0], b[njj][1], b[njj][2], b[njj][3],
                       bB + ks * 16 * BSTRIDE * 2 + njj * 32);
            #pragma unroll
            for (int mi = 0; mi < 4; mi++) {
                uint32_t a0, a1, a2, a3;
                ldsm4(a0, a1, a2, a3, aB + mi * 16 * ASTRIDE * 2 + ks * 32);
                #pragma unroll
                for (int njj = 0; njj < 2; njj++) {
                    mma_f16(acc[mi][njj*2],   a0, a1, a2, a3, b[njj][0], b[njj][1]);
                    mma_f16(acc[mi][njj*2+1], a0, a1, a2, a3, b[njj][2], b[njj][3]);
                }
            }
        }
    }

    int which = col0 >> 10;
    __half* outp = (which == 0) ? qo : (which == 1) ? ko : vo;
    float scl = (which == 0) ? 0.04508422f : 1.0f;   // E^-0.5 * log2(e)
    #pragma unroll
    for (int mi = 0; mi < 4; mi++) {
        int r = (int)row0 + wm*64 + mi*16 + (lane >> 2);
        int b0r = r / Tt, t0 = r - b0r*Tt;
        int b1r = (r+8) / Tt, t1 = (r+8) - b1r*Tt;
        #pragma unroll
        for (int nj = 0; nj < 4; nj++) {
            int c = col0 + wn*32 + nj*8 + 2*(lane & 3);
            int hd = (c >> 6) & 15, d = c & 63;
            *(uint32_t*)&outp[((size_t)(b0r*Hh + hd)*Tt + t0)*HS + d] =
                h2u(acc[mi][nj][0]*scl, acc[mi][nj][1]*scl);
            *(uint32_t*)&outp[((size_t)(b1r*Hh + hd)*Tt + t1)*HS + d] =
                h2u(acc[mi][nj][2]*scl, acc[mi][nj][3]*scl);
        }
    }
}

// ---------------- fp16 mma.sync flash attention (exp2 domain) ----------------
__global__ __launch_bounds__(128) void attn_f16(
    const __half* __restrict__ q, const __half* __restrict__ k,
    const __half* __restrict__ v, __half* __restrict__ out)
{
    __shared__ __half Qs[64*72], Ks[64*72], Vs[64*72];
    int itile = blockIdx.x, bh = blockIdx.y;
    int tid = threadIdx.x, lane = tid & 31, w = tid >> 5;
    uint32_t qb = (uint32_t)__cvta_generic_to_shared(Qs);
    uint32_t kb = (uint32_t)__cvta_generic_to_shared(Ks);
    uint32_t vb = (uint32_t)__cvta_generic_to_shared(Vs);

    const __half* Qg = q + ((size_t)bh*Tt + itile*64)*HS;
    const __half* Kg = k + (size_t)bh*Tt*HS;
    const __half* Vg = v + (size_t)bh*Tt*HS;

    for (int i = tid; i < 512; i += 128) {
        int r = i >> 3, c = (i & 7) * 8;
        *(uint4*)&Qs[r*72 + c] = *(const uint4*)&Qg[r*HS + c];
    }

    float m0 = -1e30f, m1 = -1e30f, l0 = 0.f, l1 = 0.f;
    float o[8][4];
    #pragma unroll
    for (int i = 0; i < 8; i++)
        #pragma unroll
        for (int j = 0; j < 4; j++) o[i][j] = 0.f;

    uint32_t qaddr = qb + (w*16 + (lane & 15)) * 144 + (lane >> 4) * 16;

    for (int jt = 0; jt <= itile; jt++) {
        __syncthreads();
        const __half* Kt = Kg + jt*64*HS;
        const __half* Vt = Vg + jt*64*HS;
        for (int i = tid; i < 512; i += 128) {
            int r = i >> 3, c = (i & 7) * 8;
            *(uint4*)&Ks[r*72 + c] = *(const uint4*)&Kt[r*HS + c];
            *(uint4*)&Vs[r*72 + c] = *(const uint4*)&Vt[r*HS + c];
        }
        __syncthreads();

        float s[8][4];
        #pragma unroll
        for (int i = 0; i < 8; i++)
            #pragma unroll
            for (int j = 0; j < 4; j++) s[i][j] = 0.f;

        #pragma unroll
        for (int ks = 0; ks < 4; ks++) {
            uint32_t a0, a1, a2, a3;
            ldsm4(a0, a1, a2, a3, qaddr + ks*32);
            #pragma unroll
            for (int njj = 0; njj < 4; njj++) {
                uint32_t b0, b1, b2, b3;
                ldsm4(b0, b1, b2, b3, kb + (njj*16 + (lane & 15))*144 + (lane >> 4)*16 + ks*32);
                mma_f16(s[njj*2],   a0, a1, a2, a3, b0, b2);
                mma_f16(s[njj*2+1], a0, a1, a2, a3, b1, b3);
            }
        }

        if (jt == itile) {
            int r0 = w*16 + (lane >> 2), r1 = r0 + 8;
            #pragma unroll
            for (int nj = 0; nj < 8; nj++) {
                int cb = nj*8 + 2*(lane & 3);
                if (cb   > r0) s[nj][0] = -1e30f;
                if (cb+1 > r0) s[nj][1] = -1e30f;
                if (cb   > r1) s[nj][2] = -1e30f;
                if (cb+1 > r1) s[nj][3] = -1e30f;
            }
        }

        float mx0 = -1e30f, mx1 = -1e30f;
        #pragma unroll
        for (int nj = 0; nj < 8; nj++) {
            mx0 = fmaxf(mx0, fmaxf(s[nj][0], s[nj][1]));
            mx1 = fmaxf(mx1, fmaxf(s[nj][2], s[nj][3]));
        }
        mx0 = fmaxf(mx0, __shfl_xor_sync(0xffffffffu, mx0, 1));
        mx0 = fmaxf(mx0, __shfl_xor_sync(0xffffffffu, mx0, 2));
        mx1 = fmaxf(mx1, __shfl_xor_sync(0xffffffffu, mx1, 1));
        mx1 = fmaxf(mx1, __shfl_xor_sync(0xffffffffu, mx1, 2));
        float mn0 = fmaxf(m0, mx0), mn1 = fmaxf(m1, mx1);
        float c0 = exp2f(m0 - mn0), c1 = exp2f(m1 - mn1);
        float ps0 = 0.f, ps1 = 0.f;
        #pragma unroll
        for (int nj = 0; nj < 8; nj++) {
            s[nj][0] = exp2f(s[nj][0] - mn0); ps0 += s[nj][0];
            s[nj][1] = exp2f(s[nj][1] - mn0); ps0 += s[nj][1];
            s[nj][2] = exp2f(s[nj][2] - mn1); ps1 += s[nj][2];
            s[nj][3] = exp2f(s[nj][3] - mn1); ps1 += s[nj][3];
        }
        ps0 += __shfl_xor_sync(0xffffffffu, ps0, 1);
        ps0 += __shfl_xor_sync(0xffffffffu, ps0, 2);
        ps1 += __shfl_xor_sync(0xffffffffu, ps1, 1);
        ps1 += __shfl_xor_sync(0xffffffffu, ps1, 2);
        l0 = l0*c0 + ps0; l1 = l1*c1 + ps1;
        m0 = mn0; m1 = mn1;
        #pragma unroll
        for (int nj = 0; nj < 8; nj++) {
            o[nj][0] *= c0; o[nj][1] *= c0; o[nj][2] *= c1; o[nj][3] *= c1;
        }

        #pragma unroll
        for (int ks = 0; ks < 4; ks++) {
            uint32_t pa0 = h2u(s[2*ks][0],   s[2*ks][1]);
            uint32_t pa1 = h2u(s[2*ks][2],   s[2*ks][3]);
            uint32_t pa2 = h2u(s[2*ks+1][0], s[2*ks+1][1]);
            uint32_t pa3 = h2u(s[2*ks+1][2], s[2*ks+1][3]);
            #pragma unroll
            for (int njj = 0; njj < 4; njj++) {
                uint32_t b0, b1, b2, b3;
                ldsm4t(b0, b1, b2, b3, vb + (ks*16 + (lane & 15))*144
                                           + (njj*16 + (lane >> 4)*8)*2);
                mma_f16(o[njj*2],   pa0, pa1, pa2, pa3, b0, b1);
                mma_f16(o[njj*2+1], pa0, pa1, pa2, pa3, b2, b3);
            }
        }
    }

    int b = bh >> 4, head = bh & 15;
    float inv0 = 1.0f / l0, inv1 = 1.0f / l1;
    int trow = itile*64 + w*16 + (lane >> 2);
    __half* o0p = out + ((size_t)b*Tt + trow)*Ee + head*HS;
    __half* o1p = o0p + (size_t)8*Ee;
    #pragma unroll
    for (int nj = 0; nj < 8; nj++) {
        int c = nj*8 + 2*(lane & 3);
        *(uint32_t*)&o0p[c] = h2u(o[nj][0]*inv0, o[nj][1]*inv0);
        *(uint32_t*)&o1p[c] = h2u(o[nj][2]*inv1, o[nj][3]*inv1);
    }
}

extern "C" void kernel_launch(void* const* d_in, const int* in_sizes, int n_in,
                              void* d_out, int out_size)
{
    const float* x    = (const float*)d_in[0];
    const float* Wq   = (const float*)d_in[1];
    const float* Wk   = (const float*)d_in[2];
    const float* Wv   = (const float*)d_in[3];
    const float* Wo   = (const float*)d_in[4];
    const float* bo   = (const float*)d_in[5];
    const float* W1   = (const float*)d_in[6];
    const float* b1   = (const float*)d_in[7];
    const float* W2   = (const float*)d_in[8];
    const float* b2   = (const float*)d_in[9];
    const float* ln1w = (const float*)d_in[10];
    const float* ln1b = (const float*)d_in[11];
    const float* ln2w = (const float*)d_in[12];
    const float* ln2b = (const float*)d_in[13];
    float* out = (float*)d_out;

    __half *hP, *qP, *kP, *vP, *uP, *wP;
    float *x1P;
    cudaGetSymbolAddress((void**)&hP,  g_h);
    cudaGetSymbolAddress((void**)&qP,  g_q);
    cudaGetSymbolAddress((void**)&kP,  g_k);
    cudaGetSymbolAddress((void**)&vP,  g_v);
    cudaGetSymbolAddress((void**)&x1P, g_x1);
    cudaGetSymbolAddress((void**)&uP,  g_u);
    cudaGetSymbolAddress((void**)&wP,  g_w);

    cudaFuncSetAttribute(qkv_f16, cudaFuncAttributeMaxDynamicSharedMemorySize, GEMM_SMEM);
    cudaFuncSetAttribute(gemm_f16<false,true,false>, cudaFuncAttributeMaxDynamicSharedMemorySize, GEMM_SMEM);
    cudaFuncSetAttribute(gemm_f16<true,false,true>,  cudaFuncAttributeMaxDynamicSharedMemorySize, GEMM_SMEM);

    // 1) LN1 + all weight converts in ONE launch
    prep<<<NT + 3072, 256>>>(x, ln1w, ln1b, hP,
                             (const float4*)Wq, (const float4*)Wk, (const float4*)Wv,
                             (const float4*)Wo, (const float4*)W1, (const float4*)W2,
                             (uint2*)wP);
    // 2) q,k,v = h @ Wqkv
    qkv_f16<<<dim3(NT/128, 24), 256, GEMM_SMEM>>>(hP, wP, qP, kP, vP);
    // 3) attention -> g_h
    attn_f16<<<dim3(Tt/64, Bb*Hh), 128>>>(qP, kP, vP, hP);
    // 4) x1 = x + attn @ Wo + bo
    gemm_f16<false,true,false><<<dim3(NT/128, Ee/128), 256, GEMM_SMEM>>>(
        hP, wP+WOFF_O, bo, x, x1P, Ee, Ee);
    // 5) h2 = half(LN2(x1))
    ln_h<<<NT, 256>>>(x1P, ln2w, ln2b, qP);
    // 6) u = half(relu(h2 @ W1 + b1))
    gemm_f16<true,false,true><<<dim3(NT/128, FF/128), 256, GEMM_SMEM>>>(
        qP, wP+WOFF_1, b1, nullptr, uP, Ee, FF);
    // 7) out = x1 + u @ W2 + b2
    gemm_f16<false,true,false><<<dim3(NT/128, Ee/128), 256, GEMM_SMEM>>>(
        uP, wP+WOFF_2, b2, x1P, out, FF, Ee);
}

// round 14
// speedup vs baseline: 2.1129x; 1.0983x over previous
#include <cuda_runtime.h>
#include <cuda_fp16.h>
#include <cstdint>

#define Bb   64
#define Tt   320
#define Ee   1024
#define Hh   16
#define HS   64
#define NT   (Bb*Tt)
#define FF   (4*Ee)

__device__ __half g_h [NT*Ee];
__device__ __half g_q [NT*Ee];
__device__ __half g_k [NT*Ee];
__device__ __half g_v [NT*Ee];
__device__ float  g_x1[NT*Ee];
__device__ __half g_u [NT*FF];
__device__ __half g_w [12*1024*1024];

#define WOFF_Q  0
#define WOFF_O  (3*1024*1024)
#define WOFF_1  (4*1024*1024)
#define WOFF_2  (8*1024*1024)

__device__ __forceinline__ uint32_t h2u(float lo, float hi) {
    __half2 h = __floats2half2_rn(lo, hi);
    return *reinterpret_cast<uint32_t*>(&h);
}
__device__ __forceinline__ void cpa16(uint32_t dst, const void* src) {
    asm volatile("cp.async.cg.shared.global [%0], [%1], 16;" :: "r"(dst), "l"(src));
}
__device__ __forceinline__ void cpa_commit() { asm volatile("cp.async.commit_group;"); }

__device__ __forceinline__ void mma_f16(float* c, uint32_t a0, uint32_t a1,
                                        uint32_t a2, uint32_t a3,
                                        uint32_t b0, uint32_t b1) {
    asm volatile(
        "mma.sync.aligned.m16n8k16.row.col.f32.f16.f16.f32 "
        "{%0,%1,%2,%3}, {%4,%5,%6,%7}, {%8,%9}, {%0,%1,%2,%3};"
        : "+f"(c[0]), "+f"(c[1]), "+f"(c[2]), "+f"(c[3])
        : "r"(a0), "r"(a1), "r"(a2), "r"(a3), "r"(b0), "r"(b1));
}
__device__ __forceinline__ void ldsm4(uint32_t& r0, uint32_t& r1, uint32_t& r2,
                                      uint32_t& r3, uint32_t addr) {
    asm volatile("ldmatrix.sync.aligned.m8n8.x4.shared.b16 {%0,%1,%2,%3}, [%4];"
                 : "=r"(r0), "=r"(r1), "=r"(r2), "=r"(r3) : "r"(addr));
}
__device__ __forceinline__ void ldsm4t(uint32_t& r0, uint32_t& r1, uint32_t& r2,
                                       uint32_t& r3, uint32_t addr) {
    asm volatile("ldmatrix.sync.aligned.m8n8.x4.trans.shared.b16 {%0,%1,%2,%3}, [%4];"
                 : "=r"(r0), "=r"(r1), "=r"(r2), "=r"(r3) : "r"(addr));
}

// ---------------- prep: LN1 (blocks 0..NT-1) + weight fp32->fp16 convert ----------------
__global__ __launch_bounds__(256) void prep(
    const float* __restrict__ x, const float* __restrict__ ln1w,
    const float* __restrict__ ln1b, __half* __restrict__ hout,
    const float4* __restrict__ Wq, const float4* __restrict__ Wk,
    const float4* __restrict__ Wv, const float4* __restrict__ Wo,
    const float4* __restrict__ W1, const float4* __restrict__ W2,
    uint2* __restrict__ wdst)
{
    int blk = blockIdx.x;
    int tid = threadIdx.x;
    if (blk < NT) {
        __shared__ float red0[8], red1[8];
        size_t row = blk;
        const float4* xr = reinterpret_cast<const float4*>(x + row*Ee);
        float4 v4 = xr[tid];
        float s  = v4.x + v4.y + v4.z + v4.w;
        float s2 = v4.x*v4.x + v4.y*v4.y + v4.z*v4.z + v4.w*v4.w;
        #pragma unroll
        for (int off = 16; off; off >>= 1) {
            s  += __shfl_xor_sync(0xffffffffu, s,  off);
            s2 += __shfl_xor_sync(0xffffffffu, s2, off);
        }
        if ((tid & 31) == 0) { red0[tid>>5] = s; red1[tid>>5] = s2; }
        __syncthreads();
        if (tid == 0) {
            float a = 0.f, c = 0.f;
            #pragma unroll
            for (int i = 0; i < 8; i++) { a += red0[i]; c += red1[i]; }
            red0[0] = a; red1[0] = c;
        }
        __syncthreads();
        float mu  = red0[0] * (1.0f/Ee);
        float var = red1[0] * (1.0f/Ee) - mu*mu;
        float inv = rsqrtf(var + 1e-5f);
        float4 wv = reinterpret_cast<const float4*>(ln1w)[tid];
        float4 bv = reinterpret_cast<const float4*>(ln1b)[tid];
        uint2 pk;
        pk.x = h2u((v4.x - mu)*inv*wv.x + bv.x, (v4.y - mu)*inv*wv.y + bv.y);
        pk.y = h2u((v4.z - mu)*inv*wv.z + bv.z, (v4.w - mu)*inv*wv.w + bv.w);
        reinterpret_cast<uint2*>(hout + row*Ee)[tid] = pk;
    } else {
        int cb = blk - NT;
        #pragma unroll
        for (int it = 0; it < 4; it++) {
            int i = cb*1024 + it*256 + tid;
            const float4* src; int off;
            if      (i <  262144) { src = Wq; off = i; }
            else if (i <  524288) { src = Wk; off = i -  262144; }
            else if (i <  786432) { src = Wv; off = i -  524288; }
            else if (i < 1048576) { src = Wo; off = i -  786432; }
            else if (i < 2097152) { src = W1; off = i - 1048576; }
            else                  { src = W2; off = i - 2097152; }
            float4 v = src[off];
            uint2 p; p.x = h2u(v.x, v.y); p.y = h2u(v.z, v.w);
            wdst[i] = p;
        }
    }
}

// ---------------- LayerNorm fp32 -> half (LN2) ----------------
__global__ __launch_bounds__(256) void ln_h(
    const float* __restrict__ x, const float* __restrict__ w,
    const float* __restrict__ b, __half* __restrict__ out)
{
    __shared__ float red0[8], red1[8];
    int tid = threadIdx.x;
    size_t row = blockIdx.x;
    const float4* xr = reinterpret_cast<const float4*>(x + row*Ee);
    float4 v4 = xr[tid];
    float s  = v4.x + v4.y + v4.z + v4.w;
    float s2 = v4.x*v4.x + v4.y*v4.y + v4.z*v4.z + v4.w*v4.w;
    #pragma unroll
    for (int off = 16; off; off >>= 1) {
        s  += __shfl_xor_sync(0xffffffffu, s,  off);
        s2 += __shfl_xor_sync(0xffffffffu, s2, off);
    }
    if ((tid & 31) == 0) { red0[tid>>5] = s; red1[tid>>5] = s2; }
    __syncthreads();
    if (tid == 0) {
        float a = 0.f, c = 0.f;
        #pragma unroll
        for (int i = 0; i < 8; i++) { a += red0[i]; c += red1[i]; }
        red0[0] = a; red1[0] = c;
    }
    __syncthreads();
    float mu  = red0[0] * (1.0f/Ee);
    float var = red1[0] * (1.0f/Ee) - mu*mu;
    float inv = rsqrtf(var + 1e-5f);
    float4 wv = reinterpret_cast<const float4*>(w)[tid];
    float4 bv = reinterpret_cast<const float4*>(b)[tid];
    uint2 pk;
    pk.x = h2u((v4.x - mu)*inv*wv.x + bv.x, (v4.y - mu)*inv*wv.y + bv.y);
    pk.y = h2u((v4.z - mu)*inv*wv.z + bv.z, (v4.w - mu)*inv*wv.w + bv.w);
    reinterpret_cast<uint2*>(out + row*Ee)[tid] = pk;
}

// ===== fp16 GEMM (R6 config): 128x128 CTA, BK=32, 4 stages, 8 warps of 64x32 =====
#define ASTRIDE  40                    // halfs per A smem row (80 B)
#define BSTRIDE  136                   // halfs per B smem row (272 B)
#define ABYTES   (128*ASTRIDE*2)       // 10240
#define STB      (ABYTES + 32*BSTRIDE*2)  // 18944
#define STAGES   4
#define GEMM_SMEM (STAGES*STB)         // 75776

template<bool RELU, bool RES, bool HALFOUT>
__global__ __launch_bounds__(256, 2) void gemm_f16(
    const __half* __restrict__ A, const __half* __restrict__ Bm,
    const float* __restrict__ bias, const float* __restrict__ res,
    void* __restrict__ Cout, int K, int N)
{
    extern __shared__ __half smh[];
    uint32_t smb = (uint32_t)__cvta_generic_to_shared(smh);
    int tid = threadIdx.x, lane = tid & 31, warp = tid >> 5;
    int wm = warp >> 2, wn = warp & 3;
    size_t row0 = (size_t)blockIdx.x * 128;
    int col0 = blockIdx.y * 128;

    const __half* aS0 = A + (row0 + (tid >> 2)) * (size_t)K + (tid & 3) * 8;
    const __half* aS1 = aS0 + (size_t)64 * K;
    const __half* bS0 = Bm + (size_t)(tid >> 4) * N + col0 + (tid & 15) * 8;
    const __half* bS1 = bS0 + (size_t)16 * N;
    uint32_t dA0 = smb + ((tid >> 2) * ASTRIDE + (tid & 3) * 8) * 2;
    uint32_t dA1 = dA0 + 64 * ASTRIDE * 2;
    uint32_t dB0 = smb + ABYTES + ((tid >> 4) * BSTRIDE + (tid & 15) * 8) * 2;
    uint32_t dB1 = dB0 + 16 * BSTRIDE * 2;

    float acc[4][4][4];
    #pragma unroll
    for (int i = 0; i < 4; i++)
        #pragma unroll
        for (int j = 0; j < 4; j++)
            #pragma unroll
            for (int r = 0; r < 4; r++) acc[i][j][r] = 0.f;

    const int KT = K >> 5;
    #pragma unroll
    for (int s = 0; s < STAGES - 1; s++) {
        uint32_t so = s * STB;
        cpa16(dA0 + so, aS0 + s * 32);
        cpa16(dA1 + so, aS1 + s * 32);
        cpa16(dB0 + so, bS0 + (size_t)s * 32 * N);
        cpa16(dB1 + so, bS1 + (size_t)s * 32 * N);
        cpa_commit();
    }

    uint32_t aLd = smb + (wm*64 + (lane & 15)) * ASTRIDE * 2 + (lane >> 4) * 16;
    uint32_t bLd = smb + ABYTES + (lane & 15) * BSTRIDE * 2
                       + (wn*32 + (lane >> 4) * 8) * 2;

    for (int kt = 0; kt < KT; ++kt) {
        asm volatile("cp.async.wait_group %0;" :: "n"(STAGES - 2));
        __syncthreads();
        int cur = kt % STAGES;
        int nk = kt + STAGES - 1;
        if (nk < KT) {
            uint32_t so = (nk % STAGES) * STB;
            cpa16(dA0 + so, aS0 + nk * 32);
            cpa16(dA1 + so, aS1 + nk * 32);
            cpa16(dB0 + so, bS0 + (size_t)nk * 32 * N);
            cpa16(dB1 + so, bS1 + (size_t)nk * 32 * N);
        }
        cpa_commit();

        uint32_t aB = aLd + cur * STB;
        uint32_t bB = bLd + cur * STB;
        #pragma unroll
        for (int ks = 0; ks < 2; ks++) {
            uint32_t b[2][4];
            #pragma unroll
            for (int njj = 0; njj < 2; njj++)
                ldsm4t(b[njj][0], b[njj][1], b[njj][2], b[njj][3],
                       bB + ks * 16 * BSTRIDE * 2 + njj * 32);
            #pragma unroll
            for (int mi = 0; mi < 4; mi++) {
                uint32_t a0, a1, a2, a3;
                ldsm4(a0, a1, a2, a3, aB + mi * 16 * ASTRIDE * 2 + ks * 32);
                #pragma unroll
                for (int njj = 0; njj < 2; njj++) {
                    mma_f16(acc[mi][njj*2],   a0, a1, a2, a3, b[njj][0], b[njj][1]);
                    mma_f16(acc[mi][njj*2+1], a0, a1, a2, a3, b[njj][2], b[njj][3]);
                }
            }
        }
    }

    #pragma unroll
    for (int mi = 0; mi < 4; mi++) {
        size_t r = row0 + wm*64 + mi*16 + (lane >> 2);
        #pragma unroll
        for (int nj = 0; nj < 4; nj++) {
            int c = col0 + wn*32 + nj*8 + 2*(lane & 3);
            float2 bb = *(const float2*)&bias[c];
            float v0 = acc[mi][nj][0] + bb.x, v1 = acc[mi][nj][1] + bb.y;
            float v2 = acc[mi][nj][2] + bb.x, v3 = acc[mi][nj][3] + bb.y;
            if (RELU) { v0=fmaxf(v0,0.f); v1=fmaxf(v1,0.f); v2=fmaxf(v2,0.f); v3=fmaxf(v3,0.f); }
            if (RES) {
                float2 r0 = *(const float2*)&res[r*(size_t)N + c];
                float2 r1 = *(const float2*)&res[(r+8)*(size_t)N + c];
                v0 += r0.x; v1 += r0.y; v2 += r1.x; v3 += r1.y;
            }
            if (HALFOUT) {
                __half* Ch = (__half*)Cout;
                *(uint32_t*)&Ch[r*(size_t)N + c]     = h2u(v0, v1);
                *(uint32_t*)&Ch[(r+8)*(size_t)N + c] = h2u(v2, v3);
            } else {
                float* Cf = (float*)Cout;
                float2 o0 = {v0, v1}, o1 = {v2, v3};
                *(float2*)&Cf[r*(size_t)N + c]     = o0;
                *(float2*)&Cf[(r+8)*(size_t)N + c] = o1;
            }
        }
    }
}

// ---------------- QKV projection (B per-head gather, scattered half output) ----------------
__global__ __launch_bounds__(256, 2) void qkv_f16(
    const __half* __restrict__ A, const __half* __restrict__ Wh,
    __half* __restrict__ qo, __half* __restrict__ ko, __half* __restrict__ vo)
{
    extern __shared__ __half smh[];
    uint32_t smb = (uint32_t)__cvta_generic_to_shared(smh);
    int tid = threadIdx.x, lane = tid & 31, warp = tid >> 5;
    int wm = warp >> 2, wn = warp & 3;
    size_t row0 = (size_t)blockIdx.x * 128;
    int col0 = blockIdx.y * 128;
    const int K = Ee;

    const __half* aS0 = A + (row0 + (tid >> 2)) * (size_t)K + (tid & 3) * 8;
    const __half* aS1 = aS0 + (size_t)64 * K;
    int colT = col0 + (tid & 15) * 8;
    const __half* bS0 = Wh + ((size_t)(col0 >> 10) << 20)
                           + (size_t)((colT >> 6) & 15) * (Ee*HS)
                           + (size_t)(tid >> 4) * HS + (colT & 63);
    const __half* bS1 = bS0 + 16 * HS;

    uint32_t dA0 = smb + ((tid >> 2) * ASTRIDE + (tid & 3) * 8) * 2;
    uint32_t dA1 = dA0 + 64 * ASTRIDE * 2;
    uint32_t dB0 = smb + ABYTES + ((tid >> 4) * BSTRIDE + (tid & 15) * 8) * 2;
    uint32_t dB1 = dB0 + 16 * BSTRIDE * 2;

    float acc[4][4][4];
    #pragma unroll
    for (int i = 0; i < 4; i++)
        #pragma unroll
        for (int j = 0; j < 4; j++)
            #pragma unroll
            for (int r = 0; r < 4; r++) acc[i][j][r] = 0.f;

    const int KT = K >> 5;
    #pragma unroll
    for (int s = 0; s < STAGES - 1; s++) {
        uint32_t so = s * STB;
        cpa16(dA0 + so, aS0 + s * 32);
        cpa16(dA1 + so, aS1 + s * 32);
        cpa16(dB0 + so, bS0 + s * 32 * HS);
        cpa16(dB1 + so, bS1 + s * 32 * HS);
        cpa_commit();
    }

    uint32_t aLd = smb + (wm*64 + (lane & 15)) * ASTRIDE * 2 + (lane >> 4) * 16;
    uint32_t bLd = smb + ABYTES + (lane & 15) * BSTRIDE * 2
                       + (wn*32 + (lane >> 4) * 8) * 2;

    for (int kt = 0; kt < KT; ++kt) {
        asm volatile("cp.async.wait_group %0;" :: "n"(STAGES - 2));
        __syncthreads();
        int cur = kt % STAGES;
        int nk = kt + STAGES - 1;
        if (nk < KT) {
            uint32_t so = (nk % STAGES) * STB;
            cpa16(dA0 + so, aS0 + nk * 32);
            cpa16(dA1 + so, aS1 + nk * 32);
            cpa16(dB0 + so, bS0 + nk * 32 * HS);
            cpa16(dB1 + so, bS1 + nk * 32 * HS);
        }
        cpa_commit();

        uint32_t aB = aLd + cur * STB;
        uint32_t bB = bLd + cur * STB;
        #pragma unroll
        for (int ks = 0; ks < 2; ks++) {
            uint32_t b[2][4];
            #pragma unroll
            for (int njj = 0; njj < 2; njj++)
                ldsm4t(b[njj][0], b[njj][1], b[njj][2], b[njj][3],
                       bB + ks * 16 * BSTRIDE * 2 + njj * 32);
            #pragma unroll
            for (int mi = 0; mi < 4; mi++) {
                uint32_t a0, a1, a2, a3;
                ldsm4(a0, a1, a2, a3, aB + mi * 16 * ASTRIDE * 2 + ks * 32);
                #pragma unroll
                for (int njj = 0; njj < 2; njj++) {
                    mma_f16(acc[mi][njj*2],   a0, a1, a2, a3, b[njj][0], b[njj][1]);
                    mma_f16(acc[mi][njj*2+1], a0, a1, a2, a3, b[njj][2], b[njj][3]);
                }
            }
        }
    }

    int which = col0 >> 10;
    __half* outp = (which == 0) ? qo : (which == 1) ? ko : vo;
    float scl = (which == 0) ? 0.04508422f : 1.0f;   // E^-0.5 * log2(e)
    #pragma unroll
    for (int mi = 0; mi < 4; mi++) {
        int r = (int)row0 + wm*64 + mi*16 + (lane >> 2);
        int b0r = r / Tt, t0 = r - b0r*Tt;
        int b1r = (r+8) / Tt, t1 = (r+8) - b1r*Tt;
        #pragma unroll
        for (int nj = 0; nj < 4; nj++) {
            int c = col0 + wn*32 + nj*8 + 2*(lane & 3);
            int hd = (c >> 6) & 15, d = c & 63;
            *(uint32_t*)&outp[((size_t)(b0r*Hh + hd)*Tt + t0)*HS + d] =
                h2u(acc[mi][nj][0]*scl, acc[mi][nj][1]*scl);
            *(uint32_t*)&outp[((size_t)(b1r*Hh + hd)*Tt + t1)*HS + d] =
                h2u(acc[mi][nj][2]*scl, acc[mi][nj][3]*scl);
        }
    }
}

// ---------------- fp16 flash attention, cp.async double-buffered K/V ----------------
#define KVB  (64*72*2)   // bytes per K or V buffer

__global__ __launch_bounds__(128) void attn_f16(
    const __half* __restrict__ q, const __half* __restrict__ k,
    const __half* __restrict__ v, __half* __restrict__ out)
{
    __shared__ __half Qs[64*72];
    __shared__ __half Ks[2][64*72];
    __shared__ __half Vs[2][64*72];
    int itile = blockIdx.x, bh = blockIdx.y;
    int tid = threadIdx.x, lane = tid & 31, w = tid >> 5;
    uint32_t qb = (uint32_t)__cvta_generic_to_shared(Qs);
    uint32_t kb = (uint32_t)__cvta_generic_to_shared(Ks);
    uint32_t vb = (uint32_t)__cvta_generic_to_shared(Vs);

    const __half* Qg = q + ((size_t)bh*Tt + itile*64)*HS;
    const __half* Kg = k + (size_t)bh*Tt*HS;
    const __half* Vg = v + (size_t)bh*Tt*HS;

    // load Q (direct) + prefetch K/V tile 0 (cp.async)
    for (int i = tid; i < 512; i += 128) {
        int r = i >> 3, c = (i & 7) * 8;
        *(uint4*)&Qs[r*72 + c] = *(const uint4*)&Qg[r*HS + c];
        cpa16(kb + r*144 + c*2, Kg + r*HS + c);
        cpa16(vb + r*144 + c*2, Vg + r*HS + c);
    }
    cpa_commit();

    float m0 = -1e30f, m1 = -1e30f, l0 = 0.f, l1 = 0.f;
    float o[8][4];
    #pragma unroll
    for (int i = 0; i < 8; i++)
        #pragma unroll
        for (int j = 0; j < 4; j++) o[i][j] = 0.f;

    uint32_t qaddr = qb + (w*16 + (lane & 15)) * 144 + (lane >> 4) * 16;

    for (int jt = 0; jt <= itile; jt++) {
        asm volatile("cp.async.wait_group 0;");
        __syncthreads();
        uint32_t cb = (uint32_t)(jt & 1) * KVB;

        // prefetch next tile into the other buffer (its last readers
        // finished before the barrier above)
        if (jt < itile) {
            const __half* Kt = Kg + (jt+1)*64*HS;
            const __half* Vt = Vg + (jt+1)*64*HS;
            uint32_t nb = (uint32_t)((jt+1) & 1) * KVB;
            for (int i = tid; i < 512; i += 128) {
                int r = i >> 3, c = (i & 7) * 8;
                cpa16(kb + nb + r*144 + c*2, Kt + r*HS + c);
                cpa16(vb + nb + r*144 + c*2, Vt + r*HS + c);
            }
            cpa_commit();
        }

        float s[8][4];
        #pragma unroll
        for (int i = 0; i < 8; i++)
            #pragma unroll
            for (int j = 0; j < 4; j++) s[i][j] = 0.f;

        #pragma unroll
        for (int ks = 0; ks < 4; ks++) {
            uint32_t a0, a1, a2, a3;
            ldsm4(a0, a1, a2, a3, qaddr + ks*32);
            #pragma unroll
            for (int njj = 0; njj < 4; njj++) {
                uint32_t b0, b1, b2, b3;
                ldsm4(b0, b1, b2, b3, kb + cb + (njj*16 + (lane & 15))*144
                                         + (lane >> 4)*16 + ks*32);
                mma_f16(s[njj*2],   a0, a1, a2, a3, b0, b2);
                mma_f16(s[njj*2+1], a0, a1, a2, a3, b1, b3);
            }
        }

        if (jt == itile) {
            int r0 = w*16 + (lane >> 2), r1 = r0 + 8;
            #pragma unroll
            for (int nj = 0; nj < 8; nj++) {
                int cc = nj*8 + 2*(lane & 3);
                if (cc   > r0) s[nj][0] = -1e30f;
                if (cc+1 > r0) s[nj][1] = -1e30f;
                if (cc   > r1) s[nj][2] = -1e30f;
                if (cc+1 > r1) s[nj][3] = -1e30f;
            }
        }

        float mx0 = -1e30f, mx1 = -1e30f;
        #pragma unroll
        for (int nj = 0; nj < 8; nj++) {
            mx0 = fmaxf(mx0, fmaxf(s[nj][0], s[nj][1]));
            mx1 = fmaxf(mx1, fmaxf(s[nj][2], s[nj][3]));
        }
        mx0 = fmaxf(mx0, __shfl_xor_sync(0xffffffffu, mx0, 1));
        mx0 = fmaxf(mx0, __shfl_xor_sync(0xffffffffu, mx0, 2));
        mx1 = fmaxf(mx1, __shfl_xor_sync(0xffffffffu, mx1, 1));
        mx1 = fmaxf(mx1, __shfl_xor_sync(0xffffffffu, mx1, 2));
        float mn0 = fmaxf(m0, mx0), mn1 = fmaxf(m1, mx1);
        float c0 = exp2f(m0 - mn0), c1 = exp2f(m1 - mn1);
        float ps0 = 0.f, ps1 = 0.f;
        #pragma unroll
        for (int nj = 0; nj < 8; nj++) {
            s[nj][0] = exp2f(s[nj][0] - mn0); ps0 += s[nj][0];
            s[nj][1] = exp2f(s[nj][1] - mn0); ps0 += s[nj][1];
            s[nj][2] = exp2f(s[nj][2] - mn1); ps1 += s[nj][2];
            s[nj][3] = exp2f(s[nj][3] - mn1); ps1 += s[nj][3];
        }
        ps0 += __shfl_xor_sync(0xffffffffu, ps0, 1);
        ps0 += __shfl_xor_sync(0xffffffffu, ps0, 2);
        ps1 += __shfl_xor_sync(0xffffffffu, ps1, 1);
        ps1 += __shfl_xor_sync(0xffffffffu, ps1, 2);
        l0 = l0*c0 + ps0; l1 = l1*c1 + ps1;
        m0 = mn0; m1 = mn1;
        #pragma unroll
        for (int nj = 0; nj < 8; nj++) {
            o[nj][0] *= c0; o[nj][1] *= c0; o[nj][2] *= c1; o[nj][3] *= c1;
        }

        #pragma unroll
        for (int ks = 0; ks < 4; ks++) {
            uint32_t pa0 = h2u(s[2*ks][0],   s[2*ks][1]);
            uint32_t pa1 = h2u(s[2*ks][2],   s[2*ks][3]);
            uint32_t pa2 = h2u(s[2*ks+1][0], s[2*ks+1][1]);
            uint32_t pa3 = h2u(s[2*ks+1][2], s[2*ks+1][3]);
            #pragma unroll
            for (int njj = 0; njj < 4; njj++) {
                uint32_t b0, b1, b2, b3;
                ldsm4t(b0, b1, b2, b3, vb + cb + (ks*16 + (lane & 15))*144
                                          + (njj*16 + (lane >> 4)*8)*2);
                mma_f16(o[njj*2],   pa0, pa1, pa2, pa3, b0, b1);
                mma_f16(o[njj*2+1], pa0, pa1, pa2, pa3, b2, b3);
            }
        }
    }

    int b = bh >> 4, head = bh & 15;
    float inv0 = 1.0f / l0, inv1 = 1.0f / l1;
    int trow = itile*64 + w*16 + (lane >> 2);
    __half* o0p = out + ((size_t)b*Tt + trow)*Ee + head*HS;
    __half* o1p = o0p + (size_t)8*Ee;
    #pragma unroll
    for (int nj = 0; nj < 8; nj++) {
        int c = nj*8 + 2*(lane & 3);
        *(uint32_t*)&o0p[c] = h2u(o[nj][0]*inv0, o[nj][1]*inv0);
        *(uint32_t*)&o1p[c] = h2u(o[nj][2]*inv1, o[nj][3]*inv1);
    }
}

extern "C" void kernel_launch(void* const* d_in, const int* in_sizes, int n_in,
                              void* d_out, int out_size)
{
    const float* x    = (const float*)d_in[0];
    const float* Wq   = (const float*)d_in[1];
    const float* Wk   = (const float*)d_in[2];
    const float* Wv   = (const float*)d_in[3];
    const float* Wo   = (const float*)d_in[4];
    const float* bo   = (const float*)d_in[5];
    const float* W1   = (const float*)d_in[6];
    const float* b1   = (const float*)d_in[7];
    const float* W2   = (const float*)d_in[8];
    const float* b2   = (const float*)d_in[9];
    const float* ln1w = (const float*)d_in[10];
    const float* ln1b = (const float*)d_in[11];
    const float* ln2w = (const float*)d_in[12];
    const float* ln2b = (const float*)d_in[13];
    float* out = (float*)d_out;

    __half *hP, *qP, *kP, *vP, *uP, *wP;
    float *x1P;
    cudaGetSymbolAddress((void**)&hP,  g_h);
    cudaGetSymbolAddress((void**)&qP,  g_q);
    cudaGetSymbolAddress((void**)&kP,  g_k);
    cudaGetSymbolAddress((void**)&vP,  g_v);
    cudaGetSymbolAddress((void**)&x1P, g_x1);
    cudaGetSymbolAddress((void**)&uP,  g_u);
    cudaGetSymbolAddress((void**)&wP,  g_w);

    cudaFuncSetAttribute(qkv_f16, cudaFuncAttributeMaxDynamicSharedMemorySize, GEMM_SMEM);
    cudaFuncSetAttribute(gemm_f16<false,true,false>, cudaFuncAttributeMaxDynamicSharedMemorySize, GEMM_SMEM);
    cudaFuncSetAttribute(gemm_f16<true,false,true>,  cudaFuncAttributeMaxDynamicSharedMemorySize, GEMM_SMEM);

    // 1) LN1 + all weight converts in ONE launch
    prep<<<NT + 3072, 256>>>(x, ln1w, ln1b, hP,
                             (const float4*)Wq, (const float4*)Wk, (const float4*)Wv,
                             (const float4*)Wo, (const float4*)W1, (const float4*)W2,
                             (uint2*)wP);
    // 2) q,k,v = h @ Wqkv
    qkv_f16<<<dim3(NT/128, 24), 256, GEMM_SMEM>>>(hP, wP, qP, kP, vP);
    // 3) attention -> g_h
    attn_f16<<<dim3(Tt/64, Bb*Hh), 128>>>(qP, kP, vP, hP);
    // 4) x1 = x + attn @ Wo + bo
    gemm_f16<false,true,false><<<dim3(NT/128, Ee/128), 256, GEMM_SMEM>>>(
        hP, wP+WOFF_O, bo, x, x1P, Ee, Ee);
    // 5) h2 = half(LN2(x1))
    ln_h<<<NT, 256>>>(x1P, ln2w, ln2b, qP);
    // 6) u = half(relu(h2 @ W1 + b1))
    gemm_f16<true,false,true><<<dim3(NT/128, FF/128), 256, GEMM_SMEM>>>(
        qP, wP+WOFF_1, b1, nullptr, uP, Ee, FF);
    // 7) out = x1 + u @ W2 + b2
    gemm_f16<false,true,false><<<dim3(NT/128, Ee/128), 256, GEMM_SMEM>>>(
        uP, wP+WOFF_2, b2, x1P, out, FF, Ee);
}